// round 2
// baseline (speedup 1.0000x reference)
#include <cuda_runtime.h>
#include <cuda_bf16.h>
#include <math.h>

// Problem constants
#define BATCH 8
#define HH_ 128                 // half spatial
#define P_TOT (BATCH*HH_*HH_)   // 131072 positions after DWT
#define C_DIM 64
#define IN_CH 192
#define HID_CH 384

// ---------------- scratch (static device memory; allocation-free) ----------
// Channel layouts follow the reference's interleaved flat index f = c0*4 + band:
//   g_LL [p][f]      for f in [0,64)   (orig channels 0..15, all 4 bands)
//   g_high[p][f-64]  for f in [64,256) (orig channels 16..63, all 4 bands)
__device__ __align__(16) float g_high[(size_t)P_TOT * IN_CH];   // 100.7 MB
__device__ __align__(16) float g_LL  [(size_t)P_TOT * C_DIM];   //  33.5 MB
__device__ __align__(16) float g_hid [(size_t)P_TOT * HID_CH];  // 201.3 MB
__device__ __align__(16) float g_act [(size_t)P_TOT * HID_CH];  // 201.3 MB
__device__ __align__(16) float g_enh [(size_t)P_TOT * IN_CH];   // 100.7 MB
__device__ __align__(16) float g_part[1024 * 384];              // per-(b,row) BN partials
__device__ __align__(16) float g_bns[IN_CH];
__device__ __align__(16) float g_bnb[IN_CH];

// ---------------- Kernel 1: DWT + BN partial sums --------------------------
__global__ void k_dwt(const float* __restrict__ x) {
    int bi = blockIdx.x;             // b*128 + i
    int b = bi >> 7, i = bi & 127;
    int t = threadIdx.x;             // 256
    int c = t & 63, jq = t >> 6;     // orig channel, j-phase

    // per-thread partial sums for its 4 high-band stat channels (c >= 16)
    float s0=0,s1=0,s2=0,s3=0, q0=0,q1=0,q2=0,q3=0;

    const float* xr0 = x + (size_t)(b*256 + 2*i) * 256 * 64;
    const float* xr1 = xr0 + 256*64;
    const bool isHigh = (c >= 16);
    const int f = 4*c;               // flat channel base

    for (int j = jq; j < 128; j += 4) {
        int col = 2*j*64 + c;
        float a  = xr0[col],  bb = xr0[col+64];
        float cc = xr1[col],  dd = xr1[col+64];
        float ll = 0.5f*(a+bb+cc+dd);
        float lh = 0.5f*(a-bb+cc-dd);
        float hl = 0.5f*(a+bb-cc-dd);
        float hh = 0.5f*(a-bb-cc+dd);
        size_t p = (size_t)bi*128 + j;
        float4 v = make_float4(ll, lh, hl, hh);
        if (!isHigh) {
            *(float4*)(g_LL + p*64 + f) = v;
        } else {
            *(float4*)(g_high + p*192 + (f - 64)) = v;
            s0 += ll; s1 += lh; s2 += hl; s3 += hh;
            q0 += ll*ll; q1 += lh*lh; q2 += hl*hl; q3 += hh*hh;
        }
    }

    __shared__ float red[256][8];
    red[t][0]=s0; red[t][1]=s1; red[t][2]=s2; red[t][3]=s3;
    red[t][4]=q0; red[t][5]=q1; red[t][6]=q2; red[t][7]=q3;
    __syncthreads();
    if (t >= 16 && t < 64) {
        // stat channels 4*(t-16) .. +3 (range [0,192))
        #pragma unroll
        for (int k = 0; k < 4; k++) {
            float sv = red[t][k]   + red[64+t][k]   + red[128+t][k]   + red[192+t][k];
            float qv = red[t][4+k] + red[64+t][4+k] + red[128+t][4+k] + red[192+t][4+k];
            int m = 4*(t-16) + k;
            g_part[(size_t)bi*384 + m]       = sv;
            g_part[(size_t)bi*384 + 192 + m] = qv;
        }
    }
}

// ---------------- Kernel 2: BN finalize (deterministic) --------------------
__global__ void k_bnfin(const float* __restrict__ gamma,
                        const float* __restrict__ beta) {
    int t = threadIdx.x;  // 384
    float s = 0.f;
    for (int r = 0; r < 1024; r++) s += g_part[(size_t)r*384 + t];
    __shared__ float sm[384];
    sm[t] = s;
    __syncthreads();
    if (t < 192) {
        const float N = (float)P_TOT;
        float mean = sm[t] / N;
        float var  = sm[t+192] / N - mean*mean;
        float sc   = gamma[t] * rsqrtf(var + 1e-5f);
        g_bns[t] = sc;
        g_bnb[t] = beta[t] - mean * sc;
    }
}

// ---------------- GEMM body: tile 128 pos x 64 out, KC=48 ------------------
// thread map: tx = out lane (0..15), ty = pos lane (0..15)
// each thread: 8 pos (ty + 16*pp) x 4 out (tx + 16*oo)
template<int LDK, int LDO, bool BN, bool RES>
__device__ __forceinline__ void gemm_body(const float* __restrict__ in,
                                          const float* __restrict__ w,
                                          float* __restrict__ outp,
                                          const float* __restrict__ res_scale) {
    constexpr int ROW = 52;     // 48 + pad; 52/4 = 13 (odd) -> conflict-free .128
    __shared__ float sx[128][ROW];
    __shared__ float sw[64][ROW];

    const int obase  = blockIdx.x * 64;
    const size_t pbase = (size_t)blockIdx.y * 128;
    const int t  = threadIdx.x;
    const int tx = t & 15;
    const int ty = t >> 4;

    float acc[8][4];
    #pragma unroll
    for (int pp = 0; pp < 8; pp++)
        #pragma unroll
        for (int oo = 0; oo < 4; oo++) acc[pp][oo] = 0.f;

    for (int kc = 0; kc < LDK; kc += 48) {
        // stage input tile (BN applied here if requested)
        #pragma unroll
        for (int s = 0; s < 6; s++) {
            int f  = t + 256*s;
            int p  = f / 12, kq = f % 12;
            float4 v = *(const float4*)(in + (pbase+p)*LDK + kc + 4*kq);
            if (BN) {
                float4 sc = *(const float4*)(g_bns + kc + 4*kq);
                float4 bi = *(const float4*)(g_bnb + kc + 4*kq);
                v.x = fmaf(v.x, sc.x, bi.x);
                v.y = fmaf(v.y, sc.y, bi.y);
                v.z = fmaf(v.z, sc.z, bi.z);
                v.w = fmaf(v.w, sc.w, bi.w);
            }
            *(float4*)&sx[p][4*kq] = v;
        }
        // stage weight tile
        #pragma unroll
        for (int s = 0; s < 3; s++) {
            int f = t + 256*s;
            int o = f / 12, kq = f % 12;
            *(float4*)&sw[o][4*kq] =
                *(const float4*)(w + (size_t)(obase+o)*LDK + kc + 4*kq);
        }
        __syncthreads();

        #pragma unroll
        for (int k4 = 0; k4 < 12; k4++) {
            float4 xv[8], wv[4];
            #pragma unroll
            for (int pp = 0; pp < 8; pp++)
                xv[pp] = *(const float4*)&sx[ty + 16*pp][4*k4];
            #pragma unroll
            for (int oo = 0; oo < 4; oo++)
                wv[oo] = *(const float4*)&sw[tx + 16*oo][4*k4];
            #pragma unroll
            for (int pp = 0; pp < 8; pp++)
                #pragma unroll
                for (int oo = 0; oo < 4; oo++) {
                    acc[pp][oo] = fmaf(xv[pp].x, wv[oo].x, acc[pp][oo]);
                    acc[pp][oo] = fmaf(xv[pp].y, wv[oo].y, acc[pp][oo]);
                    acc[pp][oo] = fmaf(xv[pp].z, wv[oo].z, acc[pp][oo]);
                    acc[pp][oo] = fmaf(xv[pp].w, wv[oo].w, acc[pp][oo]);
                }
        }
        __syncthreads();
    }

    float rs = 0.f;
    if (RES) rs = __ldg(res_scale);
    #pragma unroll
    for (int pp = 0; pp < 8; pp++) {
        size_t p = pbase + ty + 16*pp;
        float* orow = outp + p*LDO + obase;
        const float* hrow = g_high + p*192 + obase;  // only used if RES
        #pragma unroll
        for (int oo = 0; oo < 4; oo++) {
            int o = tx + 16*oo;
            float v = acc[pp][oo];
            if (RES) v = hrow[o] + rs * v;
            orow[o] = v;
        }
    }
}

__global__ __launch_bounds__(256, 2)
void k_gemm1(const float* __restrict__ w_in) {
    gemm_body<192, 384, true, false>(g_high, w_in, g_hid, nullptr);
}

__global__ __launch_bounds__(256, 2)
void k_gemm2(const float* __restrict__ w_out, const float* __restrict__ rs) {
    gemm_body<384, 192, false, true>(g_act, w_out, g_enh, rs);
}

// ---------------- Kernel 4: depthwise 3x3 + exact GELU ---------------------
__global__ void k_dw(const float* __restrict__ w_dw) {
    int bi = blockIdx.x;          // b*128 + i
    int i  = bi & 127;
    int ch = threadIdx.x;         // 384
    float wr[9];
    #pragma unroll
    for (int q = 0; q < 9; q++) wr[q] = w_dw[ch*9 + q];

    const float* r1 = g_hid + (size_t)bi*128*384 + ch;
    const float* r0 = r1 - 128*384;
    const float* r2 = r1 + 128*384;
    bool up = (i > 0), dn = (i < 127);

    float a0=0,a1=0,a2=0, b0=0,b1=0,b2=0, c0=0,c1=0,c2=0;
    a1 = up ? r0[0] : 0.f;  b1 = r1[0];  c1 = dn ? r2[0] : 0.f;

    float* orow = g_act + (size_t)bi*128*384 + ch;
    for (int j = 0; j < 128; j++) {
        if (j < 127) {
            int off = (j+1)*384;
            a2 = up ? r0[off] : 0.f;
            b2 = r1[off];
            c2 = dn ? r2[off] : 0.f;
        } else { a2 = 0.f; b2 = 0.f; c2 = 0.f; }
        float s = a0*wr[0] + a1*wr[1] + a2*wr[2]
                + b0*wr[3] + b1*wr[4] + b2*wr[5]
                + c0*wr[6] + c1*wr[7] + c2*wr[8];
        float g = 0.5f * s * (1.f + erff(s * 0.70710678118654752f));
        orow[(size_t)j*384] = g;
        a0=a1; a1=a2;  b0=b1; b1=b2;  c0=c1; c1=c2;
    }
}

// ---------------- Kernel 6: pixel-shuffle recombine (reference _iwt) -------
__global__ void k_iwt(float* __restrict__ out) {
    int bi = blockIdx.x;
    int b = bi >> 7, i = bi & 127;
    int t = threadIdx.x;
    int c = t & 63, jq = t >> 6;
    float* row0 = out + (size_t)(b*256 + 2*i) * 256 * 64;
    float* row1 = row0 + 256*64;
    for (int j = jq; j < 128; j += 4) {
        size_t p = (size_t)bi*128 + j;
        float ll = g_LL[p*64 + c];
        const float* e = g_enh + p*192;
        float lh = e[c], hl = e[64+c], hh = e[128+c];
        int col = 2*j*64 + c;
        row0[col]     = ll;   // (2i,   2j)   = LL
        row0[col+64]  = lh;   // (2i,   2j+1) = LHo
        row1[col]     = hl;   // (2i+1, 2j)   = HLo
        row1[col+64]  = hh;   // (2i+1, 2j+1) = HHo
    }
}

// ---------------- launch ----------------------------------------------------
extern "C" void kernel_launch(void* const* d_in, const int* in_sizes, int n_in,
                              void* d_out, int out_size) {
    const float* x     = (const float*)d_in[0];
    const float* gamma = (const float*)d_in[1];
    const float* beta  = (const float*)d_in[2];
    const float* w_in  = (const float*)d_in[3];
    const float* w_dw  = (const float*)d_in[4];
    const float* w_out = (const float*)d_in[5];
    const float* rs    = (const float*)d_in[6];
    float* out = (float*)d_out;

    k_dwt  <<<1024, 256>>>(x);
    k_bnfin<<<1,    384>>>(gamma, beta);
    k_gemm1<<<dim3(6, 1024), 256>>>(w_in);
    k_dw   <<<1024, 384>>>(w_dw);
    k_gemm2<<<dim3(3, 1024), 256>>>(w_out, rs);
    k_iwt  <<<1024, 256>>>(out);
}

// round 5
// speedup vs baseline: 1.5307x; 1.5307x over previous
#include <cuda_runtime.h>
#include <cuda_bf16.h>
#include <math.h>
#include <cstdint>

// Problem constants
#define BATCH 8
#define HH_ 128
#define P_TOT (BATCH*HH_*HH_)   // 131072 positions after DWT
#define C_DIM 64
#define IN_CH 192
#define HID_CH 384

// ---------------- scratch (static device memory; allocation-free) ----------
__device__ __align__(16) float g_high[(size_t)P_TOT * IN_CH];   // 100.7 MB
__device__ __align__(16) float g_LL  [(size_t)P_TOT * C_DIM];   //  33.5 MB
__device__ __align__(16) float g_hid [(size_t)P_TOT * HID_CH];  // 201.3 MB
__device__ __align__(16) float g_act [(size_t)P_TOT * HID_CH];  // 201.3 MB
__device__ __align__(16) float g_enh [(size_t)P_TOT * IN_CH];   // 100.7 MB
__device__ __align__(16) float g_part[1024 * 384];
__device__ __align__(16) float g_bns[IN_CH];
__device__ __align__(16) float g_bnb[IN_CH];

#define CVT_TF32(d, s) asm("cvt.rna.tf32.f32 %0, %1;" : "=r"(d) : "f"(s))

__device__ __forceinline__ void mma_tf32(float* c, const uint32_t* a, const uint32_t* b) {
    asm volatile(
        "mma.sync.aligned.m16n8k8.row.col.f32.tf32.tf32.f32 "
        "{%0,%1,%2,%3}, {%4,%5,%6,%7}, {%8,%9}, {%0,%1,%2,%3};"
        : "+f"(c[0]), "+f"(c[1]), "+f"(c[2]), "+f"(c[3])
        : "r"(a[0]), "r"(a[1]), "r"(a[2]), "r"(a[3]), "r"(b[0]), "r"(b[1]));
}

// ---------------- Kernel 1: DWT + BN partial sums --------------------------
__global__ void k_dwt(const float* __restrict__ x) {
    int bi = blockIdx.x;
    int b = bi >> 7, i = bi & 127;
    int t = threadIdx.x;
    int c = t & 63, jq = t >> 6;

    float s0=0,s1=0,s2=0,s3=0, q0=0,q1=0,q2=0,q3=0;
    const float* xr0 = x + (size_t)(b*256 + 2*i) * 256 * 64;
    const float* xr1 = xr0 + 256*64;
    const bool isHigh = (c >= 16);
    const int f = 4*c;

    for (int j = jq; j < 128; j += 4) {
        int col = 2*j*64 + c;
        float a  = xr0[col],  bb = xr0[col+64];
        float cc = xr1[col],  dd = xr1[col+64];
        float ll = 0.5f*(a+bb+cc+dd);
        float lh = 0.5f*(a-bb+cc-dd);
        float hl = 0.5f*(a+bb-cc-dd);
        float hh = 0.5f*(a-bb-cc+dd);
        size_t p = (size_t)bi*128 + j;
        float4 v = make_float4(ll, lh, hl, hh);
        if (!isHigh) {
            *(float4*)(g_LL + p*64 + f) = v;
        } else {
            *(float4*)(g_high + p*192 + (f - 64)) = v;
            s0 += ll; s1 += lh; s2 += hl; s3 += hh;
            q0 += ll*ll; q1 += lh*lh; q2 += hl*hl; q3 += hh*hh;
        }
    }

    __shared__ float red[256][8];
    red[t][0]=s0; red[t][1]=s1; red[t][2]=s2; red[t][3]=s3;
    red[t][4]=q0; red[t][5]=q1; red[t][6]=q2; red[t][7]=q3;
    __syncthreads();
    if (t >= 16 && t < 64) {
        #pragma unroll
        for (int k = 0; k < 4; k++) {
            float sv = red[t][k]   + red[64+t][k]   + red[128+t][k]   + red[192+t][k];
            float qv = red[t][4+k] + red[64+t][4+k] + red[128+t][4+k] + red[192+t][4+k];
            int m = 4*(t-16) + k;
            g_part[(size_t)bi*384 + m]       = sv;
            g_part[(size_t)bi*384 + 192 + m] = qv;
        }
    }
}

// ---------------- Kernel 2: BN finalize -------------------------------------
__global__ void k_bnfin(const float* __restrict__ gamma,
                        const float* __restrict__ beta) {
    int t = threadIdx.x;  // 384
    float s = 0.f;
    for (int r = 0; r < 1024; r++) s += g_part[(size_t)r*384 + t];
    __shared__ float sm[384];
    sm[t] = s;
    __syncthreads();
    if (t < 192) {
        const float N = (float)P_TOT;
        float mean = sm[t] / N;
        float var  = sm[t+192] / N - mean*mean;
        float sc   = gamma[t] * rsqrtf(var + 1e-5f);
        g_bns[t] = sc;
        g_bnb[t] = beta[t] - mean * sc;
    }
}

// ---------------- tf32 mma.sync GEMM core (device function) -----------------
// C[p, n] = sum_k A[p,k] * W[n,k]
// Tile: 128 pos x 64 out, BK=32. 8 warps as 4(m) x 2(n); warp tile 32x32.
template<int LDK, int LDO, bool BN, bool RES>
__device__ __forceinline__
void gemm_core(const float* __restrict__ in, const float* __restrict__ w,
               float* __restrict__ outp, const float* __restrict__ res_scale) {
    __shared__ uint32_t sA[128][36];
    __shared__ uint32_t sW[32][72];

    const int t = threadIdx.x;
    const int lane = t & 31, wp = t >> 5;
    const int warpM = (wp & 3) * 32;
    const int warpN = (wp >> 2) * 32;
    const int obase = blockIdx.x * 64;
    const size_t pbase = (size_t)blockIdx.y * 128;

    float c[2][4][4];
    #pragma unroll
    for (int mt = 0; mt < 2; mt++)
        #pragma unroll
        for (int nt = 0; nt < 4; nt++)
            #pragma unroll
            for (int q = 0; q < 4; q++) c[mt][nt][q] = 0.f;

    for (int kc = 0; kc < LDK; kc += 32) {
        // stage A: 128 rows x 32 k (BN fused, tf32 convert)
        #pragma unroll
        for (int s = 0; s < 4; s++) {
            int f = t + 256*s;
            int row = f >> 3, q = f & 7;
            float4 v = *(const float4*)(in + (pbase + row)*LDK + kc + q*4);
            if (BN) {
                float4 sc = *(const float4*)(g_bns + kc + q*4);
                float4 bi = *(const float4*)(g_bnb + kc + q*4);
                v.x = fmaf(v.x, sc.x, bi.x);
                v.y = fmaf(v.y, sc.y, bi.y);
                v.z = fmaf(v.z, sc.z, bi.z);
                v.w = fmaf(v.w, sc.w, bi.w);
            }
            uint4 u;
            CVT_TF32(u.x, v.x); CVT_TF32(u.y, v.y);
            CVT_TF32(u.z, v.z); CVT_TF32(u.w, v.w);
            *(uint4*)&sA[row][q*4] = u;
        }
        // stage W transposed: sW[k][n] = w[(obase+n)*LDK + kc + k]
        #pragma unroll
        for (int s = 0; s < 2; s++) {
            int f = t + 256*s;
            int n = f & 63, q = f >> 6;
            float4 v = *(const float4*)(w + (size_t)(obase + n)*LDK + kc + q*4);
            uint32_t u0,u1,u2,u3;
            CVT_TF32(u0, v.x); CVT_TF32(u1, v.y);
            CVT_TF32(u2, v.z); CVT_TF32(u3, v.w);
            sW[q*4+0][n] = u0; sW[q*4+1][n] = u1;
            sW[q*4+2][n] = u2; sW[q*4+3][n] = u3;
        }
        __syncthreads();

        #pragma unroll
        for (int ks = 0; ks < 4; ks++) {
            const int kk = ks*8 + (lane & 3);
            uint32_t a[2][4], b[4][2];
            #pragma unroll
            for (int mt = 0; mt < 2; mt++) {
                int r = warpM + mt*16 + (lane >> 2);
                a[mt][0] = sA[r][kk];
                a[mt][1] = sA[r+8][kk];
                a[mt][2] = sA[r][kk+4];
                a[mt][3] = sA[r+8][kk+4];
            }
            #pragma unroll
            for (int nt = 0; nt < 4; nt++) {
                int n = warpN + nt*8 + (lane >> 2);
                b[nt][0] = sW[kk][n];
                b[nt][1] = sW[kk+4][n];
            }
            #pragma unroll
            for (int mt = 0; mt < 2; mt++)
                #pragma unroll
                for (int nt = 0; nt < 4; nt++)
                    mma_tf32(c[mt][nt], a[mt], b[nt]);
        }
        __syncthreads();
    }

    // epilogue
    float rs = 0.f;
    if (RES) rs = __ldg(res_scale);
    #pragma unroll
    for (int mt = 0; mt < 2; mt++) {
        #pragma unroll
        for (int hi = 0; hi < 2; hi++) {
            int row = warpM + mt*16 + (lane >> 2) + hi*8;
            size_t p = pbase + row;
            float* orow = outp + p*LDO + obase;
            const float* hrow = g_high + p*192 + obase;  // only used if RES
            #pragma unroll
            for (int nt = 0; nt < 4; nt++) {
                int col = warpN + nt*8 + (lane & 3)*2;
                float v0 = c[mt][nt][hi*2 + 0];
                float v1 = c[mt][nt][hi*2 + 1];
                if (RES) {
                    v0 = fmaf(rs, v0, hrow[col]);
                    v1 = fmaf(rs, v1, hrow[col+1]);
                }
                *(float2*)(orow + col) = make_float2(v0, v1);
            }
        }
    }
}

// wrappers: device globals referenced from DEVICE code (host-side symbol
// addresses are invalid — that was the R3 bug)
__global__ __launch_bounds__(256)
void k_gemm1(const float* __restrict__ w_in) {
    gemm_core<192, 384, true, false>(g_high, w_in, g_hid, nullptr);
}
__global__ __launch_bounds__(256)
void k_gemm2(const float* __restrict__ w_out, const float* __restrict__ rs) {
    gemm_core<384, 192, false, true>(g_act, w_out, g_enh, rs);
}

// ---------------- Kernel 4: depthwise 3x3 + exact GELU ---------------------
// grid (1024, 2): blockIdx.y selects j half -> shorter serial chain, 2x blocks
__global__ void k_dw(const float* __restrict__ w_dw) {
    int bi = blockIdx.x;
    int i  = bi & 127;
    int jb = blockIdx.y * 64;
    int ch = threadIdx.x;         // 384
    float wr[9];
    #pragma unroll
    for (int q = 0; q < 9; q++) wr[q] = w_dw[ch*9 + q];

    const float* r1 = g_hid + (size_t)bi*128*384 + ch;
    const float* r0 = r1 - 128*384;
    const float* r2 = r1 + 128*384;
    bool up = (i > 0), dn = (i < 127);

    float a0,a1,a2, b0,b1,b2, c0,c1,c2;
    if (jb > 0) {
        int off = (jb-1)*384;
        a0 = up ? r0[off] : 0.f;  b0 = r1[off];  c0 = dn ? r2[off] : 0.f;
    } else { a0 = 0.f; b0 = 0.f; c0 = 0.f; }
    {
        int off = jb*384;
        a1 = up ? r0[off] : 0.f;  b1 = r1[off];  c1 = dn ? r2[off] : 0.f;
    }

    float* orow = g_act + (size_t)bi*128*384 + ch;
    for (int j = jb; j < jb + 64; j++) {
        if (j < 127) {
            int off = (j+1)*384;
            a2 = up ? r0[off] : 0.f;
            b2 = r1[off];
            c2 = dn ? r2[off] : 0.f;
        } else { a2 = 0.f; b2 = 0.f; c2 = 0.f; }
        float s = a0*wr[0] + a1*wr[1] + a2*wr[2]
                + b0*wr[3] + b1*wr[4] + b2*wr[5]
                + c0*wr[6] + c1*wr[7] + c2*wr[8];
        float g = 0.5f * s * (1.f + erff(s * 0.70710678118654752f));
        orow[(size_t)j*384] = g;
        a0=a1; a1=a2;  b0=b1; b1=b2;  c0=c1; c1=c2;
    }
}

// ---------------- Kernel 6: pixel-shuffle recombine -------------------------
__global__ void k_iwt(float* __restrict__ out) {
    int bi = blockIdx.x;
    int b = bi >> 7, i = bi & 127;
    int t = threadIdx.x;
    int c = t & 63, jq = t >> 6;
    float* row0 = out + (size_t)(b*256 + 2*i) * 256 * 64;
    float* row1 = row0 + 256*64;
    for (int j = jq; j < 128; j += 4) {
        size_t p = (size_t)bi*128 + j;
        float ll = g_LL[p*64 + c];
        const float* e = g_enh + p*192;
        float lh = e[c], hl = e[64+c], hh = e[128+c];
        int col = 2*j*64 + c;
        row0[col]     = ll;
        row0[col+64]  = lh;
        row1[col]     = hl;
        row1[col+64]  = hh;
    }
}

// ---------------- launch ----------------------------------------------------
extern "C" void kernel_launch(void* const* d_in, const int* in_sizes, int n_in,
                              void* d_out, int out_size) {
    const float* x     = (const float*)d_in[0];
    const float* gamma = (const float*)d_in[1];
    const float* beta  = (const float*)d_in[2];
    const float* w_in  = (const float*)d_in[3];
    const float* w_dw  = (const float*)d_in[4];
    const float* w_out = (const float*)d_in[5];
    const float* rs    = (const float*)d_in[6];
    float* out = (float*)d_out;

    k_dwt  <<<1024, 256>>>(x);
    k_bnfin<<<1,    384>>>(gamma, beta);
    k_gemm1<<<dim3(6, 1024), 256>>>(w_in);
    k_dw   <<<dim3(1024, 2), 384>>>(w_dw);
    k_gemm2<<<dim3(3, 1024), 256>>>(w_out, rs);
    k_iwt  <<<1024, 256>>>(out);
}

// round 8
// speedup vs baseline: 2.0409x; 1.3333x over previous
#include <cuda_runtime.h>
#include <cuda_fp16.h>
#include <math.h>
#include <cstdint>

#define BATCH 8
#define HH_ 128
#define P_TOT (BATCH*HH_*HH_)   // 131072
#define C_DIM 64
#define IN_CH 192
#define HID_CH 384

// ---------------- scratch ----------------------------------------------------
__device__ __align__(16) float  g_high[(size_t)P_TOT * IN_CH];      // fp32 (stats + residual)
__device__ __align__(16) float  g_LL  [(size_t)P_TOT * C_DIM];
__device__ __align__(16) float  g_hid [(size_t)P_TOT * HID_CH];     // fp32 conv input
__device__ __align__(16) float  g_enh [(size_t)P_TOT * IN_CH];
__device__ __align__(16) __half g_highbn_h[(size_t)P_TOT * IN_CH];  // BN'd, half
__device__ __align__(16) __half g_act_h[(size_t)P_TOT * HID_CH];    // gelu out, half
__device__ __align__(16) __half g_w1h[HID_CH * IN_CH];
__device__ __align__(16) __half g_w2h[IN_CH * HID_CH];
__device__ __align__(16) float  g_part[1024 * 384];
__device__ __align__(16) float  g_bns[IN_CH];
__device__ __align__(16) float  g_bnb[IN_CH];

// ---------------- helpers ----------------------------------------------------
__device__ __forceinline__ uint32_t smem_u32(const void* p) {
    uint32_t a;
    asm("{ .reg .u64 tmp; cvta.to.shared.u64 tmp, %1; cvt.u32.u64 %0, tmp; }"
        : "=r"(a) : "l"(p));
    return a;
}
#define CP_ASYNC16(dst, src) \
    asm volatile("cp.async.cg.shared.global [%0], [%1], 16;" :: "r"(dst), "l"(src))
#define CP_COMMIT()  asm volatile("cp.async.commit_group;" ::: "memory")
#define CP_WAIT1()   asm volatile("cp.async.wait_group 1;" ::: "memory")
#define CP_WAIT0()   asm volatile("cp.async.wait_group 0;" ::: "memory")

__device__ __forceinline__ void mma_f16(float* c, const uint32_t* a, const uint32_t* b) {
    asm volatile(
        "mma.sync.aligned.m16n8k16.row.col.f32.f16.f16.f32 "
        "{%0,%1,%2,%3}, {%4,%5,%6,%7}, {%8,%9}, {%0,%1,%2,%3};"
        : "+f"(c[0]), "+f"(c[1]), "+f"(c[2]), "+f"(c[3])
        : "r"(a[0]), "r"(a[1]), "r"(a[2]), "r"(a[3]), "r"(b[0]), "r"(b[1]));
}

// ---------------- Kernel 1: DWT + BN partial sums ----------------------------
__global__ void k_dwt(const float* __restrict__ x) {
    int bi = blockIdx.x;
    int b = bi >> 7, i = bi & 127;
    int t = threadIdx.x;
    int c = t & 63, jq = t >> 6;

    float s0=0,s1=0,s2=0,s3=0, q0=0,q1=0,q2=0,q3=0;
    const float* xr0 = x + (size_t)(b*256 + 2*i) * 256 * 64;
    const float* xr1 = xr0 + 256*64;
    const bool isHigh = (c >= 16);
    const int f = 4*c;

    for (int j = jq; j < 128; j += 4) {
        int col = 2*j*64 + c;
        float a  = xr0[col],  bb = xr0[col+64];
        float cc = xr1[col],  dd = xr1[col+64];
        float ll = 0.5f*(a+bb+cc+dd);
        float lh = 0.5f*(a-bb+cc-dd);
        float hl = 0.5f*(a+bb-cc-dd);
        float hh = 0.5f*(a-bb-cc+dd);
        size_t p = (size_t)bi*128 + j;
        float4 v = make_float4(ll, lh, hl, hh);
        if (!isHigh) {
            *(float4*)(g_LL + p*64 + f) = v;
        } else {
            *(float4*)(g_high + p*192 + (f - 64)) = v;
            s0 += ll; s1 += lh; s2 += hl; s3 += hh;
            q0 += ll*ll; q1 += lh*lh; q2 += hl*hl; q3 += hh*hh;
        }
    }

    __shared__ float red[256][8];
    red[t][0]=s0; red[t][1]=s1; red[t][2]=s2; red[t][3]=s3;
    red[t][4]=q0; red[t][5]=q1; red[t][6]=q2; red[t][7]=q3;
    __syncthreads();
    if (t >= 16 && t < 64) {
        #pragma unroll
        for (int k = 0; k < 4; k++) {
            float sv = red[t][k]   + red[64+t][k]   + red[128+t][k]   + red[192+t][k];
            float qv = red[t][4+k] + red[64+t][4+k] + red[128+t][4+k] + red[192+t][4+k];
            int m = 4*(t-16) + k;
            g_part[(size_t)bi*384 + m]       = sv;
            g_part[(size_t)bi*384 + 192 + m] = qv;
        }
    }
}

// ---------------- Kernel 2: BN finalize (384 threads, 1-D — max block!) ------
__global__ void k_bnfin(const float* __restrict__ gamma,
                        const float* __restrict__ beta) {
    int t = threadIdx.x;  // 384
    float s = 0.f;
    for (int r = 0; r < 1024; r++) s += g_part[(size_t)r*384 + t];
    __shared__ float sm[384];
    sm[t] = s;
    __syncthreads();
    if (t < 192) {
        const float N = (float)P_TOT;
        float mean = sm[t] / N;
        float var  = sm[t+192] / N - mean*mean;
        float sc   = gamma[t] * rsqrtf(var + 1e-5f);
        g_bns[t] = sc;
        g_bnb[t] = beta[t] - mean * sc;
    }
}

// ---------------- Kernel 2b: weights -> half ---------------------------------
__global__ void k_wcvt(const float* __restrict__ w_in, const float* __restrict__ w_out) {
    int i = blockIdx.x * 256 + threadIdx.x;   // 576 blocks -> 147456
    if (i < 73728)       g_w1h[i] = __float2half_rn(w_in[i]);
    else                 g_w2h[i - 73728] = __float2half_rn(w_out[i - 73728]);
}

// ---------------- Kernel 2c: BN apply -> half --------------------------------
__global__ void k_bnapply() {
    int idx = blockIdx.x * 256 + threadIdx.x;   // P_TOT*24
    int row = idx / 24, kq = idx % 24;
    const float* src = g_high + (size_t)row*192 + kq*8;
    float4 v0 = *(const float4*)src;
    float4 v1 = *(const float4*)(src + 4);
    float4 s0 = *(const float4*)(g_bns + kq*8);
    float4 s1 = *(const float4*)(g_bns + kq*8 + 4);
    float4 b0 = *(const float4*)(g_bnb + kq*8);
    float4 b1 = *(const float4*)(g_bnb + kq*8 + 4);
    __half2 h0 = __floats2half2_rn(fmaf(v0.x,s0.x,b0.x), fmaf(v0.y,s0.y,b0.y));
    __half2 h1 = __floats2half2_rn(fmaf(v0.z,s0.z,b0.z), fmaf(v0.w,s0.w,b0.w));
    __half2 h2 = __floats2half2_rn(fmaf(v1.x,s1.x,b1.x), fmaf(v1.y,s1.y,b1.y));
    __half2 h3 = __floats2half2_rn(fmaf(v1.z,s1.z,b1.z), fmaf(v1.w,s1.w,b1.w));
    uint4 u;
    u.x = *(uint32_t*)&h0; u.y = *(uint32_t*)&h1;
    u.z = *(uint32_t*)&h2; u.w = *(uint32_t*)&h3;
    *(uint4*)(g_highbn_h + (size_t)row*192 + kq*8) = u;
}

// ---------------- fp16 MMA GEMM: BM=64, BN=N_OUT, BK=16, cp.async 2-stage ----
// smem row: 8 data words (16 halves) + 4 pad -> stride 12; fragment-load banks
// {r*12 mod 32}+qi cover all 32 banks. Stage bytes: (64+N_OUT)*12*4.
template<int LDK, int N_OUT>
__device__ __forceinline__ void gemm_prefetch(uint32_t smem_base,
                                              const __half* __restrict__ A,
                                              const __half* __restrict__ W,
                                              size_t pbase, int t, int ic, int stage) {
    constexpr int AW  = 64 * 12;
    constexpr int STG = AW + N_OUT * 12;
    const int kc = ic * 16;
    if (t < 128) {
        int row = t >> 1, seg = t & 1;
        uint32_t dst = smem_base + (uint32_t)(stage*STG + row*12 + seg*4) * 4;
        CP_ASYNC16(dst, A + (pbase + row)*LDK + kc + seg*8);
    }
    #pragma unroll
    for (int s = 0; s < (N_OUT*2 + 255) / 256; s++) {
        int f = t + 256*s;
        if (f < N_OUT*2) {
            int n = f >> 1, seg = f & 1;
            uint32_t dst = smem_base + (uint32_t)(stage*STG + AW + n*12 + seg*4) * 4;
            CP_ASYNC16(dst, W + (size_t)n*LDK + kc + seg*8);
        }
    }
}

template<int LDK, int N_OUT, bool RES>
__device__ __forceinline__ void gemm_core(const __half* __restrict__ A,
                                          const __half* __restrict__ W,
                                          float* __restrict__ outp,
                                          const float* __restrict__ res_scale) {
    constexpr int NT  = N_OUT / 32;     // n tiles per warp (8-wide)
    constexpr int NC  = LDK / 16;       // k chunks
    constexpr int AW  = 64 * 12;
    constexpr int STG = AW + N_OUT * 12;

    extern __shared__ uint32_t smw[];
    const uint32_t smem_base = smem_u32(smw);

    const int t = threadIdx.x;
    const int lane = t & 31, wp = t >> 5;
    const int g = lane >> 2, qi = lane & 3;
    const int warpM = (wp & 1) * 32;
    const int warpN = (wp >> 1) * (N_OUT / 4);
    const size_t pbase = (size_t)blockIdx.x * 64;

    float c[2][NT][4];
    #pragma unroll
    for (int mt = 0; mt < 2; mt++)
        #pragma unroll
        for (int nt = 0; nt < NT; nt++)
            #pragma unroll
            for (int q = 0; q < 4; q++) c[mt][nt][q] = 0.f;

    gemm_prefetch<LDK, N_OUT>(smem_base, A, W, pbase, t, 0, 0);
    CP_COMMIT();

    for (int ic = 0; ic < NC; ic++) {
        if (ic + 1 < NC) {
            gemm_prefetch<LDK, N_OUT>(smem_base, A, W, pbase, t, ic+1, (ic+1)&1);
            CP_COMMIT();
            CP_WAIT1();
        } else {
            CP_WAIT0();
        }
        __syncthreads();

        const uint32_t* SA = smw + (ic & 1) * STG;
        const uint32_t* SW = SA + AW;
        uint32_t a[2][4];
        #pragma unroll
        for (int mt = 0; mt < 2; mt++) {
            int r = warpM + mt*16 + g;
            a[mt][0] = SA[r*12 + qi];
            a[mt][1] = SA[(r+8)*12 + qi];
            a[mt][2] = SA[r*12 + qi + 4];
            a[mt][3] = SA[(r+8)*12 + qi + 4];
        }
        #pragma unroll
        for (int nt = 0; nt < NT; nt++) {
            int n = warpN + nt*8 + g;
            uint32_t b[2];
            b[0] = SW[n*12 + qi];
            b[1] = SW[n*12 + qi + 4];
            mma_f16(c[0][nt], a[0], b);
            mma_f16(c[1][nt], a[1], b);
        }
        __syncthreads();
    }

    float rs = 0.f;
    if (RES) rs = __ldg(res_scale);
    #pragma unroll
    for (int mt = 0; mt < 2; mt++) {
        #pragma unroll
        for (int hi = 0; hi < 2; hi++) {
            int row = warpM + mt*16 + g + hi*8;
            size_t p = pbase + row;
            float* orow = outp + p * N_OUT;
            const float* hrow = g_high + p*192;   // used only if RES
            #pragma unroll
            for (int nt = 0; nt < NT; nt++) {
                int col = warpN + nt*8 + qi*2;
                float v0 = c[mt][nt][hi*2 + 0];
                float v1 = c[mt][nt][hi*2 + 1];
                if (RES) {
                    v0 = fmaf(rs, v0, hrow[col]);
                    v1 = fmaf(rs, v1, hrow[col+1]);
                }
                *(float2*)(orow + col) = make_float2(v0, v1);
            }
        }
    }
}

__global__ void __launch_bounds__(256, 1) k_gemm1() {
    gemm_core<192, 384, false>(g_highbn_h, g_w1h, g_hid, nullptr);
}
__global__ void __launch_bounds__(256, 2) k_gemm2(const float* __restrict__ rs) {
    gemm_core<384, 192, true>(g_act_h, g_w2h, g_enh, rs);
}

// ---------------- Kernel 4: depthwise 3x3 + exact GELU -> half ---------------
// block (96, 4): tx = 4-channel group, ty = j-quarter (32 cols); grid 1024 (bi)
__global__ void k_dw(const float* __restrict__ w_dw) {
    int bi = blockIdx.x;
    int i  = bi & 127;
    int ch = threadIdx.x * 4;
    int jb = threadIdx.y * 32;

    float w[3][3][4];
    #pragma unroll
    for (int r = 0; r < 3; r++)
        #pragma unroll
        for (int cc = 0; cc < 3; cc++)
            #pragma unroll
            for (int q = 0; q < 4; q++)
                w[r][cc][q] = w_dw[(ch+q)*9 + r*3 + cc];

    const float* r1 = g_hid + (size_t)bi*49152 + ch;
    const float* r0 = r1 - 49152;
    const float* r2 = r1 + 49152;
    const bool up = (i > 0), dn = (i < 127);

    float L[3][4], M[3][4], R[3][4];
    const float4 Z = make_float4(0,0,0,0);

#define DW_LOADCOL(dst, jj) do {                                              \
    if ((jj) >= 0 && (jj) < 128) {                                            \
        float4 _a = up ? *(const float4*)(r0 + (size_t)(jj)*384) : Z;         \
        float4 _b = *(const float4*)(r1 + (size_t)(jj)*384);                  \
        float4 _c = dn ? *(const float4*)(r2 + (size_t)(jj)*384) : Z;         \
        dst[0][0]=_a.x; dst[0][1]=_a.y; dst[0][2]=_a.z; dst[0][3]=_a.w;       \
        dst[1][0]=_b.x; dst[1][1]=_b.y; dst[1][2]=_b.z; dst[1][3]=_b.w;       \
        dst[2][0]=_c.x; dst[2][1]=_c.y; dst[2][2]=_c.z; dst[2][3]=_c.w;       \
    } else {                                                                  \
        _Pragma("unroll") for (int _r = 0; _r < 3; _r++)                      \
            _Pragma("unroll") for (int _q = 0; _q < 4; _q++) dst[_r][_q] = 0.f; \
    } } while (0)

    DW_LOADCOL(L, jb-1);
    DW_LOADCOL(M, jb);

    __half* obase = g_act_h + (size_t)bi*128*384 + ch;
    for (int j = jb; j < jb + 32; j++) {
        DW_LOADCOL(R, j+1);
        float s[4];
        #pragma unroll
        for (int q = 0; q < 4; q++) {
            float v = L[0][q]*w[0][0][q] + M[0][q]*w[0][1][q] + R[0][q]*w[0][2][q]
                    + L[1][q]*w[1][0][q] + M[1][q]*w[1][1][q] + R[1][q]*w[1][2][q]
                    + L[2][q]*w[2][0][q] + M[2][q]*w[2][1][q] + R[2][q]*w[2][2][q];
            s[q] = 0.5f * v * (1.f + erff(v * 0.70710678118654752f));
        }
        __half2 h0 = __floats2half2_rn(s[0], s[1]);
        __half2 h1 = __floats2half2_rn(s[2], s[3]);
        uint2 u;
        u.x = *(uint32_t*)&h0;
        u.y = *(uint32_t*)&h1;
        *(uint2*)(obase + (size_t)j*384) = u;
        #pragma unroll
        for (int r = 0; r < 3; r++)
            #pragma unroll
            for (int q = 0; q < 4; q++) { L[r][q] = M[r][q]; M[r][q] = R[r][q]; }
    }
#undef DW_LOADCOL
}

// ---------------- Kernel 6: pixel-shuffle recombine --------------------------
__global__ void k_iwt(float* __restrict__ out) {
    int bi = blockIdx.x;
    int b = bi >> 7, i = bi & 127;
    int t = threadIdx.x;
    int c = t & 63, jq = t >> 6;
    float* row0 = out + (size_t)(b*256 + 2*i) * 256 * 64;
    float* row1 = row0 + 256*64;
    for (int j = jq; j < 128; j += 4) {
        size_t p = (size_t)bi*128 + j;
        float ll = g_LL[p*64 + c];
        const float* e = g_enh + p*192;
        float lh = e[c], hl = e[64+c], hh = e[128+c];
        int col = 2*j*64 + c;
        row0[col]     = ll;
        row0[col+64]  = lh;
        row1[col]     = hl;
        row1[col+64]  = hh;
    }
}

// ---------------- launch ------------------------------------------------------
extern "C" void kernel_launch(void* const* d_in, const int* in_sizes, int n_in,
                              void* d_out, int out_size) {
    const float* x     = (const float*)d_in[0];
    const float* gamma = (const float*)d_in[1];
    const float* beta  = (const float*)d_in[2];
    const float* w_in  = (const float*)d_in[3];
    const float* w_dw  = (const float*)d_in[4];
    const float* w_out = (const float*)d_in[5];
    const float* rs    = (const float*)d_in[6];
    float* out = (float*)d_out;

    const int SM1 = 2 * (64*12 + 384*12) * 4;   // 43008 B (< 48K default)
    const int SM2 = 2 * (64*12 + 192*12) * 4;   // 24576 B

    k_wcvt   <<<576, 256>>>(w_in, w_out);
    k_dwt    <<<1024, 256>>>(x);
    k_bnfin  <<<1,    384>>>(gamma, beta);
    k_bnapply<<<12288, 256>>>();
    k_gemm1  <<<2048, 256, SM1>>>();
    k_dw     <<<1024, dim3(96, 4)>>>(w_dw);
    k_gemm2  <<<2048, 256, SM2>>>(rs);
    k_iwt    <<<1024, 256>>>(out);
}

// round 9
// speedup vs baseline: 2.1478x; 1.0524x over previous
#include <cuda_runtime.h>
#include <cuda_fp16.h>
#include <math.h>
#include <cstdint>

#define BATCH 8
#define HH_ 128
#define P_TOT (BATCH*HH_*HH_)   // 131072
#define C_DIM 64
#define IN_CH 192
#define HID_CH 384

// ---------------- scratch ----------------------------------------------------
__device__ __align__(16) float  g_high[(size_t)P_TOT * IN_CH];      // fp32 (stats + residual)
__device__ __align__(16) float  g_LL  [(size_t)P_TOT * C_DIM];
__device__ __align__(16) __half g_hid_h[(size_t)P_TOT * HID_CH];    // GEMM1 out, half
__device__ __align__(16) __half g_highbn_h[(size_t)P_TOT * IN_CH];  // BN'd, half
__device__ __align__(16) __half g_act_h[(size_t)P_TOT * HID_CH];    // gelu out, half
__device__ __align__(16) __half g_w1h[HID_CH * IN_CH];
__device__ __align__(16) __half g_w2h[IN_CH * HID_CH];
__device__ __align__(16) float  g_part[1024 * 384];
__device__ __align__(16) float  g_bns[IN_CH];
__device__ __align__(16) float  g_bnb[IN_CH];

// ---------------- helpers ----------------------------------------------------
__device__ __forceinline__ uint32_t smem_u32(const void* p) {
    uint32_t a;
    asm("{ .reg .u64 tmp; cvta.to.shared.u64 tmp, %1; cvt.u32.u64 %0, tmp; }"
        : "=r"(a) : "l"(p));
    return a;
}
#define CP_ASYNC16(dst, src) \
    asm volatile("cp.async.cg.shared.global [%0], [%1], 16;" :: "r"(dst), "l"(src))
#define CP_COMMIT()  asm volatile("cp.async.commit_group;" ::: "memory")
#define CP_WAIT1()   asm volatile("cp.async.wait_group 1;" ::: "memory")
#define CP_WAIT0()   asm volatile("cp.async.wait_group 0;" ::: "memory")

__device__ __forceinline__ void mma_f16(float* c, const uint32_t* a, const uint32_t* b) {
    asm volatile(
        "mma.sync.aligned.m16n8k16.row.col.f32.f16.f16.f32 "
        "{%0,%1,%2,%3}, {%4,%5,%6,%7}, {%8,%9}, {%0,%1,%2,%3};"
        : "+f"(c[0]), "+f"(c[1]), "+f"(c[2]), "+f"(c[3])
        : "r"(a[0]), "r"(a[1]), "r"(a[2]), "r"(a[3]), "r"(b[0]), "r"(b[1]));
}

// ---------------- Kernel 1: DWT + BN partial sums ----------------------------
__global__ void k_dwt(const float* __restrict__ x) {
    int bi = blockIdx.x;
    int b = bi >> 7, i = bi & 127;
    int t = threadIdx.x;
    int c = t & 63, jq = t >> 6;

    float s0=0,s1=0,s2=0,s3=0, q0=0,q1=0,q2=0,q3=0;
    const float* xr0 = x + (size_t)(b*256 + 2*i) * 256 * 64;
    const float* xr1 = xr0 + 256*64;
    const bool isHigh = (c >= 16);
    const int f = 4*c;

    for (int j = jq; j < 128; j += 4) {
        int col = 2*j*64 + c;
        float a  = xr0[col],  bb = xr0[col+64];
        float cc = xr1[col],  dd = xr1[col+64];
        float ll = 0.5f*(a+bb+cc+dd);
        float lh = 0.5f*(a-bb+cc-dd);
        float hl = 0.5f*(a+bb-cc-dd);
        float hh = 0.5f*(a-bb-cc+dd);
        size_t p = (size_t)bi*128 + j;
        float4 v = make_float4(ll, lh, hl, hh);
        if (!isHigh) {
            *(float4*)(g_LL + p*64 + f) = v;
        } else {
            *(float4*)(g_high + p*192 + (f - 64)) = v;
            s0 += ll; s1 += lh; s2 += hl; s3 += hh;
            q0 += ll*ll; q1 += lh*lh; q2 += hl*hl; q3 += hh*hh;
        }
    }

    __shared__ float red[256][8];
    red[t][0]=s0; red[t][1]=s1; red[t][2]=s2; red[t][3]=s3;
    red[t][4]=q0; red[t][5]=q1; red[t][6]=q2; red[t][7]=q3;
    __syncthreads();
    if (t >= 16 && t < 64) {
        #pragma unroll
        for (int k = 0; k < 4; k++) {
            float sv = red[t][k]   + red[64+t][k]   + red[128+t][k]   + red[192+t][k];
            float qv = red[t][4+k] + red[64+t][4+k] + red[128+t][4+k] + red[192+t][4+k];
            int m = 4*(t-16) + k;
            g_part[(size_t)bi*384 + m]       = sv;
            g_part[(size_t)bi*384 + 192 + m] = qv;
        }
    }
}

// ---------------- Kernel 2: BN finalize (384 threads, 1-D) -------------------
__global__ void k_bnfin(const float* __restrict__ gamma,
                        const float* __restrict__ beta) {
    int t = threadIdx.x;  // 384
    float s = 0.f;
    for (int r = 0; r < 1024; r++) s += g_part[(size_t)r*384 + t];
    __shared__ float sm[384];
    sm[t] = s;
    __syncthreads();
    if (t < 192) {
        const float N = (float)P_TOT;
        float mean = sm[t] / N;
        float var  = sm[t+192] / N - mean*mean;
        float sc   = gamma[t] * rsqrtf(var + 1e-5f);
        g_bns[t] = sc;
        g_bnb[t] = beta[t] - mean * sc;
    }
}

// ---------------- Kernel 2b: weights -> half ---------------------------------
__global__ void k_wcvt(const float* __restrict__ w_in, const float* __restrict__ w_out) {
    int i = blockIdx.x * 256 + threadIdx.x;   // 576 blocks -> 147456
    if (i < 73728)       g_w1h[i] = __float2half_rn(w_in[i]);
    else                 g_w2h[i - 73728] = __float2half_rn(w_out[i - 73728]);
}

// ---------------- Kernel 2c: BN apply -> half --------------------------------
__global__ void k_bnapply() {
    int idx = blockIdx.x * 256 + threadIdx.x;   // P_TOT*24
    int row = idx / 24, kq = idx % 24;
    const float* src = g_high + (size_t)row*192 + kq*8;
    float4 v0 = *(const float4*)src;
    float4 v1 = *(const float4*)(src + 4);
    float4 s0 = *(const float4*)(g_bns + kq*8);
    float4 s1 = *(const float4*)(g_bns + kq*8 + 4);
    float4 b0 = *(const float4*)(g_bnb + kq*8);
    float4 b1 = *(const float4*)(g_bnb + kq*8 + 4);
    __half2 h0 = __floats2half2_rn(fmaf(v0.x,s0.x,b0.x), fmaf(v0.y,s0.y,b0.y));
    __half2 h1 = __floats2half2_rn(fmaf(v0.z,s0.z,b0.z), fmaf(v0.w,s0.w,b0.w));
    __half2 h2 = __floats2half2_rn(fmaf(v1.x,s1.x,b1.x), fmaf(v1.y,s1.y,b1.y));
    __half2 h3 = __floats2half2_rn(fmaf(v1.z,s1.z,b1.z), fmaf(v1.w,s1.w,b1.w));
    uint4 u;
    u.x = *(uint32_t*)&h0; u.y = *(uint32_t*)&h1;
    u.z = *(uint32_t*)&h2; u.w = *(uint32_t*)&h3;
    *(uint4*)(g_highbn_h + (size_t)row*192 + kq*8) = u;
}

// ---------------- fp16 MMA GEMM: BM=64, BN=N_OUT, BK=16, cp.async 2-stage ----
// MODE 0: store half -> g_hid_h.  MODE 1: residual + fused iwt scatter -> out.
template<int LDK, int N_OUT>
__device__ __forceinline__ void gemm_prefetch(uint32_t smem_base,
                                              const __half* __restrict__ A,
                                              const __half* __restrict__ W,
                                              size_t pbase, int t, int ic, int stage) {
    constexpr int AW  = 64 * 12;
    constexpr int STG = AW + N_OUT * 12;
    const int kc = ic * 16;
    if (t < 128) {
        int row = t >> 1, seg = t & 1;
        uint32_t dst = smem_base + (uint32_t)(stage*STG + row*12 + seg*4) * 4;
        CP_ASYNC16(dst, A + (pbase + row)*LDK + kc + seg*8);
    }
    #pragma unroll
    for (int s = 0; s < (N_OUT*2 + 255) / 256; s++) {
        int f = t + 256*s;
        if (f < N_OUT*2) {
            int n = f >> 1, seg = f & 1;
            uint32_t dst = smem_base + (uint32_t)(stage*STG + AW + n*12 + seg*4) * 4;
            CP_ASYNC16(dst, W + (size_t)n*LDK + kc + seg*8);
        }
    }
}

template<int LDK, int N_OUT, int MODE>
__device__ __forceinline__ void gemm_core(const __half* __restrict__ A,
                                          const __half* __restrict__ W,
                                          __half* __restrict__ out_h,
                                          float* __restrict__ out_f,
                                          const float* __restrict__ res_scale) {
    constexpr int NT  = N_OUT / 32;
    constexpr int NC  = LDK / 16;
    constexpr int AW  = 64 * 12;
    constexpr int STG = AW + N_OUT * 12;

    extern __shared__ uint32_t smw[];
    const uint32_t smem_base = smem_u32(smw);

    const int t = threadIdx.x;
    const int lane = t & 31, wp = t >> 5;
    const int g = lane >> 2, qi = lane & 3;
    const int warpM = (wp & 1) * 32;
    const int warpN = (wp >> 1) * (N_OUT / 4);
    const size_t pbase = (size_t)blockIdx.x * 64;

    float c[2][NT][4];
    #pragma unroll
    for (int mt = 0; mt < 2; mt++)
        #pragma unroll
        for (int nt = 0; nt < NT; nt++)
            #pragma unroll
            for (int q = 0; q < 4; q++) c[mt][nt][q] = 0.f;

    gemm_prefetch<LDK, N_OUT>(smem_base, A, W, pbase, t, 0, 0);
    CP_COMMIT();

    for (int ic = 0; ic < NC; ic++) {
        if (ic + 1 < NC) {
            gemm_prefetch<LDK, N_OUT>(smem_base, A, W, pbase, t, ic+1, (ic+1)&1);
            CP_COMMIT();
            CP_WAIT1();
        } else {
            CP_WAIT0();
        }
        __syncthreads();

        const uint32_t* SA = smw + (ic & 1) * STG;
        const uint32_t* SW = SA + AW;
        uint32_t a[2][4];
        #pragma unroll
        for (int mt = 0; mt < 2; mt++) {
            int r = warpM + mt*16 + g;
            a[mt][0] = SA[r*12 + qi];
            a[mt][1] = SA[(r+8)*12 + qi];
            a[mt][2] = SA[r*12 + qi + 4];
            a[mt][3] = SA[(r+8)*12 + qi + 4];
        }
        #pragma unroll
        for (int nt = 0; nt < NT; nt++) {
            int n = warpN + nt*8 + g;
            uint32_t b[2];
            b[0] = SW[n*12 + qi];
            b[1] = SW[n*12 + qi + 4];
            mma_f16(c[0][nt], a[0], b);
            mma_f16(c[1][nt], a[1], b);
        }
        __syncthreads();
    }

    if (MODE == 0) {
        // store half to g_hid_h
        #pragma unroll
        for (int mt = 0; mt < 2; mt++) {
            #pragma unroll
            for (int hi = 0; hi < 2; hi++) {
                int row = warpM + mt*16 + g + hi*8;
                __half* orow = out_h + (pbase + row) * N_OUT;
                #pragma unroll
                for (int nt = 0; nt < NT; nt++) {
                    int col = warpN + nt*8 + qi*2;
                    __half2 hv = __floats2half2_rn(c[mt][nt][hi*2], c[mt][nt][hi*2+1]);
                    *(__half2*)(orow + col) = hv;
                }
            }
        }
    } else {
        // residual + fused pixel-shuffle scatter into final output
        const float rs = __ldg(res_scale);
        #pragma unroll
        for (int mt = 0; mt < 2; mt++) {
            #pragma unroll
            for (int hi = 0; hi < 2; hi++) {
                int row = warpM + mt*16 + g + hi*8;
                size_t p = pbase + row;
                int bi = (int)(p >> 7);
                int j  = (int)(p & 127);
                int b  = bi >> 7, i = bi & 127;
                const float* hrow = g_high + p*192;
                // base addr of out[b][2i][2j][0]
                size_t base = ((size_t)(b*256 + 2*i) * 256 + 2*j) * 64;
                #pragma unroll
                for (int nt = 0; nt < NT; nt++) {
                    int col = warpN + nt*8 + qi*2;
                    int gq = col >> 6, cc = col & 63;
                    float v0 = fmaf(rs, c[mt][nt][hi*2 + 0], hrow[col]);
                    float v1 = fmaf(rs, c[mt][nt][hi*2 + 1], hrow[col+1]);
                    // gq=0 (LH) -> (2i, 2j+1); gq=1 (HL) -> (2i+1, 2j); gq=2 (HH) -> (2i+1, 2j+1)
                    size_t addr = base + cc
                                + ((gq >= 1) ? (size_t)256*64 : 0)
                                + ((gq != 1) ? 64 : 0);
                    *(float2*)(out_f + addr) = make_float2(v0, v1);
                }
            }
        }
    }
}

__global__ void __launch_bounds__(256, 1) k_gemm1() {
    gemm_core<192, 384, 0>(g_highbn_h, g_w1h, g_hid_h, nullptr, nullptr);
}
__global__ void __launch_bounds__(256, 2) k_gemm2(float* __restrict__ out,
                                                  const float* __restrict__ rs) {
    gemm_core<384, 192, 1>(g_act_h, g_w2h, nullptr, out, rs);
}

// ---------------- Kernel 4: depthwise 3x3 + exact GELU (half in/out) ---------
// block (96, 4): tx = 4-channel group, ty = j-quarter (32 cols); grid 1024 (bi)
__global__ void k_dw(const float* __restrict__ w_dw) {
    int bi = blockIdx.x;
    int i  = bi & 127;
    int ch = threadIdx.x * 4;
    int jb = threadIdx.y * 32;

    float w[3][3][4];
    #pragma unroll
    for (int r = 0; r < 3; r++)
        #pragma unroll
        for (int cc = 0; cc < 3; cc++)
            #pragma unroll
            for (int q = 0; q < 4; q++)
                w[r][cc][q] = w_dw[(ch+q)*9 + r*3 + cc];

    const __half* r1 = g_hid_h + (size_t)bi*49152 + ch;
    const __half* r0 = r1 - 49152;
    const __half* r2 = r1 + 49152;
    const bool up = (i > 0), dn = (i < 127);

    float L[3][4], M[3][4], R[3][4];

#define DW_CVT(dst, u) do {                                                   \
    __half2 _h0 = *(__half2*)&(u).x, _h1 = *(__half2*)&(u).y;                 \
    float2 _f0 = __half22float2(_h0), _f1 = __half22float2(_h1);              \
    dst[0] = _f0.x; dst[1] = _f0.y; dst[2] = _f1.x; dst[3] = _f1.y;           \
} while (0)

#define DW_LOADCOL(dst, jj) do {                                              \
    if ((jj) >= 0 && (jj) < 128) {                                            \
        uint2 _zz = make_uint2(0, 0);                                         \
        uint2 _ua = up ? *(const uint2*)(r0 + (size_t)(jj)*384) : _zz;        \
        uint2 _ub = *(const uint2*)(r1 + (size_t)(jj)*384);                   \
        uint2 _uc = dn ? *(const uint2*)(r2 + (size_t)(jj)*384) : _zz;        \
        DW_CVT(dst[0], _ua); DW_CVT(dst[1], _ub); DW_CVT(dst[2], _uc);        \
    } else {                                                                  \
        _Pragma("unroll") for (int _r = 0; _r < 3; _r++)                      \
            _Pragma("unroll") for (int _q = 0; _q < 4; _q++) dst[_r][_q] = 0.f; \
    } } while (0)

    DW_LOADCOL(L, jb-1);
    DW_LOADCOL(M, jb);

    __half* obase = g_act_h + (size_t)bi*128*384 + ch;
    for (int j = jb; j < jb + 32; j++) {
        DW_LOADCOL(R, j+1);
        float s[4];
        #pragma unroll
        for (int q = 0; q < 4; q++) {
            float v = L[0][q]*w[0][0][q] + M[0][q]*w[0][1][q] + R[0][q]*w[0][2][q]
                    + L[1][q]*w[1][0][q] + M[1][q]*w[1][1][q] + R[1][q]*w[1][2][q]
                    + L[2][q]*w[2][0][q] + M[2][q]*w[2][1][q] + R[2][q]*w[2][2][q];
            s[q] = 0.5f * v * (1.f + erff(v * 0.70710678118654752f));
        }
        __half2 h0 = __floats2half2_rn(s[0], s[1]);
        __half2 h1 = __floats2half2_rn(s[2], s[3]);
        uint2 u;
        u.x = *(uint32_t*)&h0;
        u.y = *(uint32_t*)&h1;
        *(uint2*)(obase + (size_t)j*384) = u;
        #pragma unroll
        for (int r = 0; r < 3; r++)
            #pragma unroll
            for (int q = 0; q < 4; q++) { L[r][q] = M[r][q]; M[r][q] = R[r][q]; }
    }
#undef DW_LOADCOL
#undef DW_CVT
}

// ---------------- Kernel 6: LL quadrant only (rest fused into GEMM2) ---------
__global__ void k_ll(float* __restrict__ out) {
    int bi = blockIdx.x;
    int b = bi >> 7, i = bi & 127;
    int t = threadIdx.x;
    int c = t & 63, jq = t >> 6;
    float* row0 = out + (size_t)(b*256 + 2*i) * 256 * 64;
    for (int j = jq; j < 128; j += 4) {
        size_t p = (size_t)bi*128 + j;
        row0[2*j*64 + c] = g_LL[p*64 + c];
    }
}

// ---------------- launch ------------------------------------------------------
extern "C" void kernel_launch(void* const* d_in, const int* in_sizes, int n_in,
                              void* d_out, int out_size) {
    const float* x     = (const float*)d_in[0];
    const float* gamma = (const float*)d_in[1];
    const float* beta  = (const float*)d_in[2];
    const float* w_in  = (const float*)d_in[3];
    const float* w_dw  = (const float*)d_in[4];
    const float* w_out = (const float*)d_in[5];
    const float* rs    = (const float*)d_in[6];
    float* out = (float*)d_out;

    const int SM1 = 2 * (64*12 + 384*12) * 4;   // 43008 B (< 48K default)
    const int SM2 = 2 * (64*12 + 192*12) * 4;   // 24576 B

    k_wcvt   <<<576, 256>>>(w_in, w_out);
    k_dwt    <<<1024, 256>>>(x);
    k_bnfin  <<<1,    384>>>(gamma, beta);
    k_bnapply<<<12288, 256>>>();
    k_gemm1  <<<2048, 256, SM1>>>();
    k_dw     <<<1024, dim3(96, 4)>>>(w_dw);
    k_ll     <<<1024, 256>>>(out);
    k_gemm2  <<<2048, 256, SM2>>>(out, rs);
}

// round 10
// speedup vs baseline: 2.4024x; 1.1185x over previous
#include <cuda_runtime.h>
#include <cuda_fp16.h>
#include <math.h>
#include <cstdint>

#define BATCH 8
#define HH_ 128
#define P_TOT (BATCH*HH_*HH_)   // 131072
#define C_DIM 64
#define IN_CH 192
#define HID_CH 384

// ---------------- scratch ----------------------------------------------------
__device__ __align__(16) __half g_high_h[(size_t)P_TOT * IN_CH];    // half (BN input + residual)
__device__ __align__(16) __half g_hid_h[(size_t)P_TOT * HID_CH];    // GEMM1 out
__device__ __align__(16) __half g_highbn_h[(size_t)P_TOT * IN_CH];  // BN'd
__device__ __align__(16) __half g_act_h[(size_t)P_TOT * HID_CH];    // gelu out
__device__ __align__(16) __half g_w1h[HID_CH * IN_CH];
__device__ __align__(16) __half g_w2h[IN_CH * HID_CH];
__device__ __align__(16) float  g_part[1024 * 384];
__device__ __align__(16) float  g_bns[IN_CH];
__device__ __align__(16) float  g_bnb[IN_CH];

// ---------------- helpers ----------------------------------------------------
__device__ __forceinline__ uint32_t smem_u32(const void* p) {
    uint32_t a;
    asm("{ .reg .u64 tmp; cvta.to.shared.u64 tmp, %1; cvt.u32.u64 %0, tmp; }"
        : "=r"(a) : "l"(p));
    return a;
}
#define CP_ASYNC16(dst, src) \
    asm volatile("cp.async.cg.shared.global [%0], [%1], 16;" :: "r"(dst), "l"(src))
#define CP_COMMIT()  asm volatile("cp.async.commit_group;" ::: "memory")
#define CP_WAIT1()   asm volatile("cp.async.wait_group 1;" ::: "memory")
#define CP_WAIT0()   asm volatile("cp.async.wait_group 0;" ::: "memory")

__device__ __forceinline__ void ldsm_x4(uint32_t& r0, uint32_t& r1,
                                        uint32_t& r2, uint32_t& r3, uint32_t addr) {
    asm volatile("ldmatrix.sync.aligned.m8n8.x4.shared.b16 {%0,%1,%2,%3}, [%4];"
        : "=r"(r0), "=r"(r1), "=r"(r2), "=r"(r3) : "r"(addr));
}

__device__ __forceinline__ void mma_f16(float* c, const uint32_t* a, const uint32_t* b) {
    asm volatile(
        "mma.sync.aligned.m16n8k16.row.col.f32.f16.f16.f32 "
        "{%0,%1,%2,%3}, {%4,%5,%6,%7}, {%8,%9}, {%0,%1,%2,%3};"
        : "+f"(c[0]), "+f"(c[1]), "+f"(c[2]), "+f"(c[3])
        : "r"(a[0]), "r"(a[1]), "r"(a[2]), "r"(a[3]), "r"(b[0]), "r"(b[1]));
}

// ---------------- Kernel 1: DWT + BN partials; LL straight into out ----------
__global__ void k_dwt(const float* __restrict__ x, float* __restrict__ out) {
    int bi = blockIdx.x;
    int b = bi >> 7, i = bi & 127;
    int t = threadIdx.x;
    int c = t & 63, jq = t >> 6;

    float s0=0,s1=0,s2=0,s3=0, q0=0,q1=0,q2=0,q3=0;
    const float* xr0 = x + (size_t)(b*256 + 2*i) * 256 * 64;
    const float* xr1 = xr0 + 256*64;
    float* orow0 = out + (size_t)(b*256 + 2*i) * 256 * 64;
    const bool isHigh = (c >= 16);
    const int f = 4*c;

    for (int j = jq; j < 128; j += 4) {
        int col = 2*j*64 + c;
        float a  = xr0[col],  bb = xr0[col+64];
        float cc = xr1[col],  dd = xr1[col+64];
        float ll = 0.5f*(a+bb+cc+dd);
        float lh = 0.5f*(a-bb+cc-dd);
        float hl = 0.5f*(a+bb-cc-dd);
        float hh = 0.5f*(a-bb-cc+dd);
        size_t p = (size_t)bi*128 + j;
        if (!isHigh) {
            // LL flat channels f..f+3 -> out[b][2i][2j][f..f+3]
            *(float4*)(orow0 + 2*j*64 + f) = make_float4(ll, lh, hl, hh);
        } else {
            __half2 h0 = __floats2half2_rn(ll, lh);
            __half2 h1 = __floats2half2_rn(hl, hh);
            uint2 u;
            u.x = *(uint32_t*)&h0;
            u.y = *(uint32_t*)&h1;
            *(uint2*)(g_high_h + p*192 + (f - 64)) = u;
            s0 += ll; s1 += lh; s2 += hl; s3 += hh;
            q0 += ll*ll; q1 += lh*lh; q2 += hl*hl; q3 += hh*hh;
        }
    }

    __shared__ float red[256][8];
    red[t][0]=s0; red[t][1]=s1; red[t][2]=s2; red[t][3]=s3;
    red[t][4]=q0; red[t][5]=q1; red[t][6]=q2; red[t][7]=q3;
    __syncthreads();
    if (t >= 16 && t < 64) {
        #pragma unroll
        for (int k = 0; k < 4; k++) {
            float sv = red[t][k]   + red[64+t][k]   + red[128+t][k]   + red[192+t][k];
            float qv = red[t][4+k] + red[64+t][4+k] + red[128+t][4+k] + red[192+t][4+k];
            int m = 4*(t-16) + k;
            g_part[(size_t)bi*384 + m]       = sv;
            g_part[(size_t)bi*384 + 192 + m] = qv;
        }
    }
}

// ---------------- Kernel 2: BN finalize --------------------------------------
__global__ void k_bnfin(const float* __restrict__ gamma,
                        const float* __restrict__ beta) {
    int t = threadIdx.x;  // 384
    float s = 0.f;
    for (int r = 0; r < 1024; r++) s += g_part[(size_t)r*384 + t];
    __shared__ float sm[384];
    sm[t] = s;
    __syncthreads();
    if (t < 192) {
        const float N = (float)P_TOT;
        float mean = sm[t] / N;
        float var  = sm[t+192] / N - mean*mean;
        float sc   = gamma[t] * rsqrtf(var + 1e-5f);
        g_bns[t] = sc;
        g_bnb[t] = beta[t] - mean * sc;
    }
}

// ---------------- Kernel 2b: weights -> half ---------------------------------
__global__ void k_wcvt(const float* __restrict__ w_in, const float* __restrict__ w_out) {
    int i = blockIdx.x * 256 + threadIdx.x;   // 576 blocks
    if (i < 73728)       g_w1h[i] = __float2half_rn(w_in[i]);
    else                 g_w2h[i - 73728] = __float2half_rn(w_out[i - 73728]);
}

// ---------------- Kernel 2c: BN apply (half in -> half out) ------------------
__global__ void k_bnapply() {
    int idx = blockIdx.x * 256 + threadIdx.x;   // P_TOT*24 threads, 8 ch each
    int row = idx / 24, kq = idx % 24;
    uint4 u = *(const uint4*)(g_high_h + (size_t)row*192 + kq*8);
    float4 s0 = *(const float4*)(g_bns + kq*8);
    float4 s1 = *(const float4*)(g_bns + kq*8 + 4);
    float4 b0 = *(const float4*)(g_bnb + kq*8);
    float4 b1 = *(const float4*)(g_bnb + kq*8 + 4);
    float2 f0 = __half22float2(*(__half2*)&u.x);
    float2 f1 = __half22float2(*(__half2*)&u.y);
    float2 f2 = __half22float2(*(__half2*)&u.z);
    float2 f3 = __half22float2(*(__half2*)&u.w);
    __half2 h0 = __floats2half2_rn(fmaf(f0.x,s0.x,b0.x), fmaf(f0.y,s0.y,b0.y));
    __half2 h1 = __floats2half2_rn(fmaf(f1.x,s0.z,b0.z), fmaf(f1.y,s0.w,b0.w));
    __half2 h2 = __floats2half2_rn(fmaf(f2.x,s1.x,b1.x), fmaf(f2.y,s1.y,b1.y));
    __half2 h3 = __floats2half2_rn(fmaf(f3.x,s1.z,b1.z), fmaf(f3.y,s1.w,b1.w));
    uint4 o;
    o.x = *(uint32_t*)&h0; o.y = *(uint32_t*)&h1;
    o.z = *(uint32_t*)&h2; o.w = *(uint32_t*)&h3;
    *(uint4*)(g_highbn_h + (size_t)row*192 + kq*8) = o;
}

// ---------------- fp16 MMA GEMM: BM=64, BN=N_OUT, BK=16, cp.async, ldmatrix --
template<int LDK, int N_OUT>
__device__ __forceinline__ void gemm_prefetch(uint32_t smem_base,
                                              const __half* __restrict__ A,
                                              const __half* __restrict__ W,
                                              size_t pbase, int t, int ic, int stage) {
    constexpr int AW  = 64 * 12;
    constexpr int STG = AW + N_OUT * 12;
    const int kc = ic * 16;
    if (t < 128) {
        int row = t >> 1, seg = t & 1;
        uint32_t dst = smem_base + (uint32_t)(stage*STG + row*12 + seg*4) * 4;
        CP_ASYNC16(dst, A + (pbase + row)*LDK + kc + seg*8);
    }
    #pragma unroll
    for (int s = 0; s < (N_OUT*2 + 255) / 256; s++) {
        int f = t + 256*s;
        if (f < N_OUT*2) {
            int n = f >> 1, seg = f & 1;
            uint32_t dst = smem_base + (uint32_t)(stage*STG + AW + n*12 + seg*4) * 4;
            CP_ASYNC16(dst, W + (size_t)n*LDK + kc + seg*8);
        }
    }
}

template<int LDK, int N_OUT, int MODE>
__device__ __forceinline__ void gemm_core(const __half* __restrict__ A,
                                          const __half* __restrict__ W,
                                          __half* __restrict__ out_h,
                                          float* __restrict__ out_f,
                                          const float* __restrict__ res_scale) {
    constexpr int NT  = N_OUT / 32;
    constexpr int NC  = LDK / 16;
    constexpr int AW  = 64 * 12;
    constexpr int STG = AW + N_OUT * 12;

    extern __shared__ uint32_t smw[];
    const uint32_t smem_base = smem_u32(smw);

    const int t = threadIdx.x;
    const int lane = t & 31, wp = t >> 5;
    const int g = lane >> 2, qi = lane & 3;
    const int warpM = (wp & 1) * 32;
    const int warpN = (wp >> 1) * (N_OUT / 4);
    const size_t pbase = (size_t)blockIdx.x * 64;

    // ldmatrix per-lane addresses (byte offsets)
    uint32_t aAddr[2];
    #pragma unroll
    for (int mt = 0; mt < 2; mt++) {
        int row  = warpM + mt*16 + (lane & 7) + ((lane >> 3) & 1) * 8;
        int word = (lane & 16) ? 4 : 0;
        aAddr[mt] = smem_base + (uint32_t)(row*12 + word) * 4;
    }
    uint32_t bAddr[NT/2];
    #pragma unroll
    for (int ntp = 0; ntp < NT/2; ntp++) {
        int row  = warpN + ntp*16 + ((lane >> 4) & 1) * 8 + (lane & 7);
        int word = ((lane >> 3) & 1) * 4;
        bAddr[ntp] = smem_base + (uint32_t)(AW + row*12 + word) * 4;
    }

    float c[2][NT][4];
    #pragma unroll
    for (int mt = 0; mt < 2; mt++)
        #pragma unroll
        for (int nt = 0; nt < NT; nt++)
            #pragma unroll
            for (int q = 0; q < 4; q++) c[mt][nt][q] = 0.f;

    gemm_prefetch<LDK, N_OUT>(smem_base, A, W, pbase, t, 0, 0);
    CP_COMMIT();

    for (int ic = 0; ic < NC; ic++) {
        if (ic + 1 < NC) {
            gemm_prefetch<LDK, N_OUT>(smem_base, A, W, pbase, t, ic+1, (ic+1)&1);
            CP_COMMIT();
            CP_WAIT1();
        } else {
            CP_WAIT0();
        }
        __syncthreads();

        const uint32_t soff = (uint32_t)((ic & 1) * STG * 4);
        uint32_t a[2][4];
        ldsm_x4(a[0][0], a[0][1], a[0][2], a[0][3], aAddr[0] + soff);
        ldsm_x4(a[1][0], a[1][1], a[1][2], a[1][3], aAddr[1] + soff);
        #pragma unroll
        for (int ntp = 0; ntp < NT/2; ntp++) {
            uint32_t b0, b1, b2, b3;
            ldsm_x4(b0, b1, b2, b3, bAddr[ntp] + soff);
            uint32_t bb0[2] = {b0, b1}, bb1[2] = {b2, b3};
            mma_f16(c[0][2*ntp],   a[0], bb0);
            mma_f16(c[1][2*ntp],   a[1], bb0);
            mma_f16(c[0][2*ntp+1], a[0], bb1);
            mma_f16(c[1][2*ntp+1], a[1], bb1);
        }
        __syncthreads();
    }

    if (MODE == 0) {
        #pragma unroll
        for (int mt = 0; mt < 2; mt++) {
            #pragma unroll
            for (int hi = 0; hi < 2; hi++) {
                int row = warpM + mt*16 + g + hi*8;
                __half* orow = out_h + (pbase + row) * N_OUT;
                #pragma unroll
                for (int nt = 0; nt < NT; nt++) {
                    int col = warpN + nt*8 + qi*2;
                    __half2 hv = __floats2half2_rn(c[mt][nt][hi*2], c[mt][nt][hi*2+1]);
                    *(__half2*)(orow + col) = hv;
                }
            }
        }
    } else {
        // residual (half) + fused pixel-shuffle scatter to final output
        const float rs = __ldg(res_scale);
        #pragma unroll
        for (int mt = 0; mt < 2; mt++) {
            #pragma unroll
            for (int hi = 0; hi < 2; hi++) {
                int row = warpM + mt*16 + g + hi*8;
                size_t p = pbase + row;
                int bi = (int)(p >> 7);
                int j  = (int)(p & 127);
                int b  = bi >> 7, i = bi & 127;
                const __half* hrow = g_high_h + p*192;
                size_t base = ((size_t)(b*256 + 2*i) * 256 + 2*j) * 64;
                #pragma unroll
                for (int nt = 0; nt < NT; nt++) {
                    int col = warpN + nt*8 + qi*2;
                    int gq = col >> 6, cc = col & 63;
                    float2 hv = __half22float2(*(const __half2*)(hrow + col));
                    float v0 = fmaf(rs, c[mt][nt][hi*2 + 0], hv.x);
                    float v1 = fmaf(rs, c[mt][nt][hi*2 + 1], hv.y);
                    size_t addr = base + cc
                                + ((gq >= 1) ? (size_t)256*64 : 0)
                                + ((gq != 1) ? 64 : 0);
                    *(float2*)(out_f + addr) = make_float2(v0, v1);
                }
            }
        }
    }
}

__global__ void __launch_bounds__(256, 1) k_gemm1() {
    gemm_core<192, 384, 0>(g_highbn_h, g_w1h, g_hid_h, nullptr, nullptr);
}
__global__ void __launch_bounds__(256, 2) k_gemm2(float* __restrict__ out,
                                                  const float* __restrict__ rs) {
    gemm_core<384, 192, 1>(g_act_h, g_w2h, nullptr, out, rs);
}

// ---------------- Kernel 4: depthwise 3x3 + exact GELU (half in/out) ---------
__global__ void k_dw(const float* __restrict__ w_dw) {
    int bi = blockIdx.x;
    int i  = bi & 127;
    int ch = threadIdx.x * 4;
    int jb = threadIdx.y * 32;

    float w[3][3][4];
    #pragma unroll
    for (int r = 0; r < 3; r++)
        #pragma unroll
        for (int cc = 0; cc < 3; cc++)
            #pragma unroll
            for (int q = 0; q < 4; q++)
                w[r][cc][q] = w_dw[(ch+q)*9 + r*3 + cc];

    const __half* r1 = g_hid_h + (size_t)bi*49152 + ch;
    const __half* r0 = r1 - 49152;
    const __half* r2 = r1 + 49152;
    const bool up = (i > 0), dn = (i < 127);

    float L[3][4], M[3][4], R[3][4];

#define DW_CVT(dst, u) do {                                                   \
    __half2 _h0 = *(__half2*)&(u).x, _h1 = *(__half2*)&(u).y;                 \
    float2 _f0 = __half22float2(_h0), _f1 = __half22float2(_h1);              \
    dst[0] = _f0.x; dst[1] = _f0.y; dst[2] = _f1.x; dst[3] = _f1.y;           \
} while (0)

#define DW_LOADCOL(dst, jj) do {                                              \
    if ((jj) >= 0 && (jj) < 128) {                                            \
        uint2 _zz = make_uint2(0, 0);                                         \
        uint2 _ua = up ? *(const uint2*)(r0 + (size_t)(jj)*384) : _zz;        \
        uint2 _ub = *(const uint2*)(r1 + (size_t)(jj)*384);                   \
        uint2 _uc = dn ? *(const uint2*)(r2 + (size_t)(jj)*384) : _zz;        \
        DW_CVT(dst[0], _ua); DW_CVT(dst[1], _ub); DW_CVT(dst[2], _uc);        \
    } else {                                                                  \
        _Pragma("unroll") for (int _r = 0; _r < 3; _r++)                      \
            _Pragma("unroll") for (int _q = 0; _q < 4; _q++) dst[_r][_q] = 0.f; \
    } } while (0)

    DW_LOADCOL(L, jb-1);
    DW_LOADCOL(M, jb);

    __half* obase = g_act_h + (size_t)bi*128*384 + ch;
    for (int j = jb; j < jb + 32; j++) {
        DW_LOADCOL(R, j+1);
        float s[4];
        #pragma unroll
        for (int q = 0; q < 4; q++) {
            float v = L[0][q]*w[0][0][q] + M[0][q]*w[0][1][q] + R[0][q]*w[0][2][q]
                    + L[1][q]*w[1][0][q] + M[1][q]*w[1][1][q] + R[1][q]*w[1][2][q]
                    + L[2][q]*w[2][0][q] + M[2][q]*w[2][1][q] + R[2][q]*w[2][2][q];
            s[q] = 0.5f * v * (1.f + erff(v * 0.70710678118654752f));
        }
        __half2 h0 = __floats2half2_rn(s[0], s[1]);
        __half2 h1 = __floats2half2_rn(s[2], s[3]);
        uint2 u;
        u.x = *(uint32_t*)&h0;
        u.y = *(uint32_t*)&h1;
        *(uint2*)(obase + (size_t)j*384) = u;
        #pragma unroll
        for (int r = 0; r < 3; r++)
            #pragma unroll
            for (int q = 0; q < 4; q++) { L[r][q] = M[r][q]; M[r][q] = R[r][q]; }
    }
#undef DW_LOADCOL
#undef DW_CVT
}

// ---------------- launch ------------------------------------------------------
extern "C" void kernel_launch(void* const* d_in, const int* in_sizes, int n_in,
                              void* d_out, int out_size) {
    const float* x     = (const float*)d_in[0];
    const float* gamma = (const float*)d_in[1];
    const float* beta  = (const float*)d_in[2];
    const float* w_in  = (const float*)d_in[3];
    const float* w_dw  = (const float*)d_in[4];
    const float* w_out = (const float*)d_in[5];
    const float* rs    = (const float*)d_in[6];
    float* out = (float*)d_out;

    const int SM1 = 2 * (64*12 + 384*12) * 4;   // 43008 B
    const int SM2 = 2 * (64*12 + 192*12) * 4;   // 24576 B

    k_wcvt   <<<576, 256>>>(w_in, w_out);
    k_dwt    <<<1024, 256>>>(x, out);
    k_bnfin  <<<1,    384>>>(gamma, beta);
    k_bnapply<<<12288, 256>>>();
    k_gemm1  <<<2048, 256, SM1>>>();
    k_dw     <<<1024, dim3(96, 4)>>>(w_dw);
    k_gemm2  <<<2048, 256, SM2>>>(out, rs);
}

// round 11
// speedup vs baseline: 2.4899x; 1.0364x over previous
#include <cuda_runtime.h>
#include <cuda_fp16.h>
#include <math.h>
#include <cstdint>

#define BATCH 8
#define HH_ 128
#define P_TOT (BATCH*HH_*HH_)   // 131072
#define C_DIM 64
#define IN_CH 192
#define HID_CH 384

// ---------------- scratch ----------------------------------------------------
__device__ __align__(16) __half g_high_h[(size_t)P_TOT * IN_CH];    // raw high bands (GEMM1 in + residual)
__device__ __align__(16) __half g_hid_h[(size_t)P_TOT * HID_CH];    // GEMM1 out
__device__ __align__(16) __half g_act_h[(size_t)P_TOT * HID_CH];    // gelu out
__device__ __align__(16) __half g_w1h[HID_CH * IN_CH];              // BN-folded w_in
__device__ __align__(16) __half g_w2h[IN_CH * HID_CH];
__device__ __align__(16) float  g_bias1[HID_CH];                    // BN-folded bias
__device__ __align__(16) float  g_part[1024 * 384];
__device__ __align__(16) float  g_bns[IN_CH];
__device__ __align__(16) float  g_bnb[IN_CH];

// ---------------- helpers ----------------------------------------------------
__device__ __forceinline__ uint32_t smem_u32(const void* p) {
    uint32_t a;
    asm("{ .reg .u64 tmp; cvta.to.shared.u64 tmp, %1; cvt.u32.u64 %0, tmp; }"
        : "=r"(a) : "l"(p));
    return a;
}
#define CP_ASYNC16(dst, src) \
    asm volatile("cp.async.cg.shared.global [%0], [%1], 16;" :: "r"(dst), "l"(src))
#define CP_COMMIT()  asm volatile("cp.async.commit_group;" ::: "memory")
#define CP_WAIT1()   asm volatile("cp.async.wait_group 1;" ::: "memory")
#define CP_WAIT0()   asm volatile("cp.async.wait_group 0;" ::: "memory")

__device__ __forceinline__ void ldsm_x4(uint32_t& r0, uint32_t& r1,
                                        uint32_t& r2, uint32_t& r3, uint32_t addr) {
    asm volatile("ldmatrix.sync.aligned.m8n8.x4.shared.b16 {%0,%1,%2,%3}, [%4];"
        : "=r"(r0), "=r"(r1), "=r"(r2), "=r"(r3) : "r"(addr));
}

__device__ __forceinline__ void mma_f16(float* c, const uint32_t* a, const uint32_t* b) {
    asm volatile(
        "mma.sync.aligned.m16n8k16.row.col.f32.f16.f16.f32 "
        "{%0,%1,%2,%3}, {%4,%5,%6,%7}, {%8,%9}, {%0,%1,%2,%3};"
        : "+f"(c[0]), "+f"(c[1]), "+f"(c[2]), "+f"(c[3])
        : "r"(a[0]), "r"(a[1]), "r"(a[2]), "r"(a[3]), "r"(b[0]), "r"(b[1]));
}

// ---------------- Kernel 1: DWT + BN partials; LL straight into out ----------
__global__ void k_dwt(const float* __restrict__ x, float* __restrict__ out) {
    int bi = blockIdx.x;
    int b = bi >> 7, i = bi & 127;
    int t = threadIdx.x;
    int c = t & 63, jq = t >> 6;

    float s0=0,s1=0,s2=0,s3=0, q0=0,q1=0,q2=0,q3=0;
    const float* xr0 = x + (size_t)(b*256 + 2*i) * 256 * 64;
    const float* xr1 = xr0 + 256*64;
    float* orow0 = out + (size_t)(b*256 + 2*i) * 256 * 64;
    const bool isHigh = (c >= 16);
    const int f = 4*c;

    for (int j = jq; j < 128; j += 4) {
        int col = 2*j*64 + c;
        float a  = xr0[col],  bb = xr0[col+64];
        float cc = xr1[col],  dd = xr1[col+64];
        float ll = 0.5f*(a+bb+cc+dd);
        float lh = 0.5f*(a-bb+cc-dd);
        float hl = 0.5f*(a+bb-cc-dd);
        float hh = 0.5f*(a-bb-cc+dd);
        size_t p = (size_t)bi*128 + j;
        if (!isHigh) {
            *(float4*)(orow0 + 2*j*64 + f) = make_float4(ll, lh, hl, hh);
        } else {
            __half2 h0 = __floats2half2_rn(ll, lh);
            __half2 h1 = __floats2half2_rn(hl, hh);
            uint2 u;
            u.x = *(uint32_t*)&h0;
            u.y = *(uint32_t*)&h1;
            *(uint2*)(g_high_h + p*192 + (f - 64)) = u;
            s0 += ll; s1 += lh; s2 += hl; s3 += hh;
            q0 += ll*ll; q1 += lh*lh; q2 += hl*hl; q3 += hh*hh;
        }
    }

    __shared__ float red[256][8];
    red[t][0]=s0; red[t][1]=s1; red[t][2]=s2; red[t][3]=s3;
    red[t][4]=q0; red[t][5]=q1; red[t][6]=q2; red[t][7]=q3;
    __syncthreads();
    if (t >= 16 && t < 64) {
        #pragma unroll
        for (int k = 0; k < 4; k++) {
            float sv = red[t][k]   + red[64+t][k]   + red[128+t][k]   + red[192+t][k];
            float qv = red[t][4+k] + red[64+t][4+k] + red[128+t][4+k] + red[192+t][4+k];
            int m = 4*(t-16) + k;
            g_part[(size_t)bi*384 + m]       = sv;
            g_part[(size_t)bi*384 + 192 + m] = qv;
        }
    }
}

// ---------------- Kernel 2: BN finalize --------------------------------------
__global__ void k_bnfin(const float* __restrict__ gamma,
                        const float* __restrict__ beta) {
    int t = threadIdx.x;  // 384
    float s = 0.f;
    for (int r = 0; r < 1024; r++) s += g_part[(size_t)r*384 + t];
    __shared__ float sm[384];
    sm[t] = s;
    __syncthreads();
    if (t < 192) {
        const float N = (float)P_TOT;
        float mean = sm[t] / N;
        float var  = sm[t+192] / N - mean*mean;
        float sc   = gamma[t] * rsqrtf(var + 1e-5f);
        g_bns[t] = sc;
        g_bnb[t] = beta[t] - mean * sc;
    }
}

// ---------------- Kernel 3: weight prep (BN fold + half convert) -------------
// blocks [0,384): w1 row o -> g_w1h (scaled) + g_bias1[o]
// blocks [384,768): w2 convert
__global__ void k_wprep(const float* __restrict__ w_in,
                        const float* __restrict__ w_out) {
    int b = blockIdx.x, t = threadIdx.x;   // 192 threads
    if (b < 384) {
        float wv = w_in[b*192 + t];
        g_w1h[b*192 + t] = __float2half_rn(wv * g_bns[t]);
        float p = wv * g_bnb[t];
        #pragma unroll
        for (int o = 16; o; o >>= 1) p += __shfl_down_sync(0xffffffffu, p, o);
        __shared__ float sw[6];
        if ((t & 31) == 0) sw[t >> 5] = p;
        __syncthreads();
        if (t == 0)
            g_bias1[b] = sw[0]+sw[1]+sw[2]+sw[3]+sw[4]+sw[5];
    } else {
        int i = (b - 384)*192 + t;
        g_w2h[i] = __float2half_rn(w_out[i]);
    }
}

// ---------------- fp16 MMA GEMM: BM=64, BN=N_OUT, BK=16, cp.async, ldmatrix --
template<int LDK, int N_OUT>
__device__ __forceinline__ void gemm_prefetch(uint32_t smem_base,
                                              const __half* __restrict__ A,
                                              const __half* __restrict__ W,
                                              size_t pbase, int t, int ic, int stage) {
    constexpr int AW  = 64 * 12;
    constexpr int STG = AW + N_OUT * 12;
    const int kc = ic * 16;
    if (t < 128) {
        int row = t >> 1, seg = t & 1;
        uint32_t dst = smem_base + (uint32_t)(stage*STG + row*12 + seg*4) * 4;
        CP_ASYNC16(dst, A + (pbase + row)*LDK + kc + seg*8);
    }
    #pragma unroll
    for (int s = 0; s < (N_OUT*2 + 255) / 256; s++) {
        int f = t + 256*s;
        if (f < N_OUT*2) {
            int n = f >> 1, seg = f & 1;
            uint32_t dst = smem_base + (uint32_t)(stage*STG + AW + n*12 + seg*4) * 4;
            CP_ASYNC16(dst, W + (size_t)n*LDK + kc + seg*8);
        }
    }
}

// MODE 0: +bias, store half -> g_hid_h.  MODE 1: residual + fused iwt scatter.
template<int LDK, int N_OUT, int MODE>
__device__ __forceinline__ void gemm_core(const __half* __restrict__ A,
                                          const __half* __restrict__ W,
                                          __half* __restrict__ out_h,
                                          float* __restrict__ out_f,
                                          const float* __restrict__ res_scale) {
    constexpr int NT  = N_OUT / 32;
    constexpr int NC  = LDK / 16;
    constexpr int AW  = 64 * 12;
    constexpr int STG = AW + N_OUT * 12;

    extern __shared__ uint32_t smw[];
    const uint32_t smem_base = smem_u32(smw);

    const int t = threadIdx.x;
    const int lane = t & 31, wp = t >> 5;
    const int g = lane >> 2, qi = lane & 3;
    const int warpM = (wp & 1) * 32;
    const int warpN = (wp >> 1) * (N_OUT / 4);
    const size_t pbase = (size_t)blockIdx.x * 64;

    uint32_t aAddr[2];
    #pragma unroll
    for (int mt = 0; mt < 2; mt++) {
        int row  = warpM + mt*16 + (lane & 7) + ((lane >> 3) & 1) * 8;
        int word = (lane & 16) ? 4 : 0;
        aAddr[mt] = smem_base + (uint32_t)(row*12 + word) * 4;
    }
    uint32_t bAddr[NT/2];
    #pragma unroll
    for (int ntp = 0; ntp < NT/2; ntp++) {
        int row  = warpN + ntp*16 + ((lane >> 4) & 1) * 8 + (lane & 7);
        int word = ((lane >> 3) & 1) * 4;
        bAddr[ntp] = smem_base + (uint32_t)(AW + row*12 + word) * 4;
    }

    float c[2][NT][4];
    #pragma unroll
    for (int mt = 0; mt < 2; mt++)
        #pragma unroll
        for (int nt = 0; nt < NT; nt++)
            #pragma unroll
            for (int q = 0; q < 4; q++) c[mt][nt][q] = 0.f;

    gemm_prefetch<LDK, N_OUT>(smem_base, A, W, pbase, t, 0, 0);
    CP_COMMIT();

    for (int ic = 0; ic < NC; ic++) {
        if (ic + 1 < NC) {
            gemm_prefetch<LDK, N_OUT>(smem_base, A, W, pbase, t, ic+1, (ic+1)&1);
            CP_COMMIT();
            CP_WAIT1();
        } else {
            CP_WAIT0();
        }
        __syncthreads();

        const uint32_t soff = (uint32_t)((ic & 1) * STG * 4);
        uint32_t a[2][4];
        ldsm_x4(a[0][0], a[0][1], a[0][2], a[0][3], aAddr[0] + soff);
        ldsm_x4(a[1][0], a[1][1], a[1][2], a[1][3], aAddr[1] + soff);
        #pragma unroll
        for (int ntp = 0; ntp < NT/2; ntp++) {
            uint32_t b0, b1, b2, b3;
            ldsm_x4(b0, b1, b2, b3, bAddr[ntp] + soff);
            uint32_t bb0[2] = {b0, b1}, bb1[2] = {b2, b3};
            mma_f16(c[0][2*ntp],   a[0], bb0);
            mma_f16(c[1][2*ntp],   a[1], bb0);
            mma_f16(c[0][2*ntp+1], a[0], bb1);
            mma_f16(c[1][2*ntp+1], a[1], bb1);
        }
        __syncthreads();
    }

    if (MODE == 0) {
        #pragma unroll
        for (int mt = 0; mt < 2; mt++) {
            #pragma unroll
            for (int hi = 0; hi < 2; hi++) {
                int row = warpM + mt*16 + g + hi*8;
                __half* orow = out_h + (pbase + row) * N_OUT;
                #pragma unroll
                for (int nt = 0; nt < NT; nt++) {
                    int col = warpN + nt*8 + qi*2;
                    float2 bv = *(const float2*)(g_bias1 + col);
                    __half2 hv = __floats2half2_rn(c[mt][nt][hi*2]   + bv.x,
                                                   c[mt][nt][hi*2+1] + bv.y);
                    *(__half2*)(orow + col) = hv;
                }
            }
        }
    } else {
        const float rs = __ldg(res_scale);
        #pragma unroll
        for (int mt = 0; mt < 2; mt++) {
            #pragma unroll
            for (int hi = 0; hi < 2; hi++) {
                int row = warpM + mt*16 + g + hi*8;
                size_t p = pbase + row;
                int bi = (int)(p >> 7);
                int j  = (int)(p & 127);
                int b  = bi >> 7, i = bi & 127;
                const __half* hrow = g_high_h + p*192;
                size_t base = ((size_t)(b*256 + 2*i) * 256 + 2*j) * 64;
                #pragma unroll
                for (int nt = 0; nt < NT; nt++) {
                    int col = warpN + nt*8 + qi*2;
                    int gq = col >> 6, cc = col & 63;
                    float2 hv = __half22float2(*(const __half2*)(hrow + col));
                    float v0 = fmaf(rs, c[mt][nt][hi*2 + 0], hv.x);
                    float v1 = fmaf(rs, c[mt][nt][hi*2 + 1], hv.y);
                    size_t addr = base + cc
                                + ((gq >= 1) ? (size_t)256*64 : 0)
                                + ((gq != 1) ? 64 : 0);
                    *(float2*)(out_f + addr) = make_float2(v0, v1);
                }
            }
        }
    }
}

__global__ void __launch_bounds__(256, 1) k_gemm1() {
    gemm_core<192, 384, 0>(g_high_h, g_w1h, g_hid_h, nullptr, nullptr);
}
__global__ void __launch_bounds__(256, 2) k_gemm2(float* __restrict__ out,
                                                  const float* __restrict__ rs) {
    gemm_core<384, 192, 1>(g_act_h, g_w2h, nullptr, out, rs);
}

// ---------------- Kernel 4: depthwise 3x3 + exact GELU (half in/out) ---------
__global__ void k_dw(const float* __restrict__ w_dw) {
    int bi = blockIdx.x;
    int i  = bi & 127;
    int ch = threadIdx.x * 4;
    int jb = threadIdx.y * 32;

    float w[3][3][4];
    #pragma unroll
    for (int r = 0; r < 3; r++)
        #pragma unroll
        for (int cc = 0; cc < 3; cc++)
            #pragma unroll
            for (int q = 0; q < 4; q++)
                w[r][cc][q] = w_dw[(ch+q)*9 + r*3 + cc];

    const __half* r1 = g_hid_h + (size_t)bi*49152 + ch;
    const __half* r0 = r1 - 49152;
    const __half* r2 = r1 + 49152;
    const bool up = (i > 0), dn = (i < 127);

    float L[3][4], M[3][4], R[3][4];

#define DW_CVT(dst, u) do {                                                   \
    __half2 _h0 = *(__half2*)&(u).x, _h1 = *(__half2*)&(u).y;                 \
    float2 _f0 = __half22float2(_h0), _f1 = __half22float2(_h1);              \
    dst[0] = _f0.x; dst[1] = _f0.y; dst[2] = _f1.x; dst[3] = _f1.y;           \
} while (0)

#define DW_LOADCOL(dst, jj) do {                                              \
    if ((jj) >= 0 && (jj) < 128) {                                            \
        uint2 _zz = make_uint2(0, 0);                                         \
        uint2 _ua = up ? *(const uint2*)(r0 + (size_t)(jj)*384) : _zz;        \
        uint2 _ub = *(const uint2*)(r1 + (size_t)(jj)*384);                   \
        uint2 _uc = dn ? *(const uint2*)(r2 + (size_t)(jj)*384) : _zz;        \
        DW_CVT(dst[0], _ua); DW_CVT(dst[1], _ub); DW_CVT(dst[2], _uc);        \
    } else {                                                                  \
        _Pragma("unroll") for (int _r = 0; _r < 3; _r++)                      \
            _Pragma("unroll") for (int _q = 0; _q < 4; _q++) dst[_r][_q] = 0.f; \
    } } while (0)

    DW_LOADCOL(L, jb-1);
    DW_LOADCOL(M, jb);

    __half* obase = g_act_h + (size_t)bi*128*384 + ch;
    for (int j = jb; j < jb + 32; j++) {
        DW_LOADCOL(R, j+1);
        float s[4];
        #pragma unroll
        for (int q = 0; q < 4; q++) {
            float v = L[0][q]*w[0][0][q] + M[0][q]*w[0][1][q] + R[0][q]*w[0][2][q]
                    + L[1][q]*w[1][0][q] + M[1][q]*w[1][1][q] + R[1][q]*w[1][2][q]
                    + L[2][q]*w[2][0][q] + M[2][q]*w[2][1][q] + R[2][q]*w[2][2][q];
            s[q] = 0.5f * v * (1.f + erff(v * 0.70710678118654752f));
        }
        __half2 h0 = __floats2half2_rn(s[0], s[1]);
        __half2 h1 = __floats2half2_rn(s[2], s[3]);
        uint2 u;
        u.x = *(uint32_t*)&h0;
        u.y = *(uint32_t*)&h1;
        *(uint2*)(obase + (size_t)j*384) = u;
        #pragma unroll
        for (int r = 0; r < 3; r++)
            #pragma unroll
            for (int q = 0; q < 4; q++) { L[r][q] = M[r][q]; M[r][q] = R[r][q]; }
    }
#undef DW_LOADCOL
#undef DW_CVT
}

// ---------------- launch ------------------------------------------------------
extern "C" void kernel_launch(void* const* d_in, const int* in_sizes, int n_in,
                              void* d_out, int out_size) {
    const float* x     = (const float*)d_in[0];
    const float* gamma = (const float*)d_in[1];
    const float* beta  = (const float*)d_in[2];
    const float* w_in  = (const float*)d_in[3];
    const float* w_dw  = (const float*)d_in[4];
    const float* w_out = (const float*)d_in[5];
    const float* rs    = (const float*)d_in[6];
    float* out = (float*)d_out;

    const int SM1 = 2 * (64*12 + 384*12) * 4;   // 43008 B
    const int SM2 = 2 * (64*12 + 192*12) * 4;   // 24576 B

    k_dwt  <<<1024, 256>>>(x, out);
    k_bnfin<<<1,    384>>>(gamma, beta);
    k_wprep<<<768,  192>>>(w_in, w_out);
    k_gemm1<<<2048, 256, SM1>>>();
    k_dw   <<<1024, dim3(96, 4)>>>(w_dw);
    k_gemm2<<<2048, 256, SM2>>>(out, rs);
}

// round 12
// speedup vs baseline: 2.5838x; 1.0377x over previous
#include <cuda_runtime.h>
#include <cuda_fp16.h>
#include <math.h>
#include <cstdint>

#define BATCH 8
#define HH_ 128
#define P_TOT (BATCH*HH_*HH_)   // 131072
#define C_DIM 64
#define IN_CH 192
#define HID_CH 384

// ---------------- scratch ----------------------------------------------------
__device__ __align__(16) __half g_high_h[(size_t)P_TOT * IN_CH];
__device__ __align__(16) __half g_hid_h[(size_t)P_TOT * HID_CH];
__device__ __align__(16) __half g_act_h[(size_t)P_TOT * HID_CH];
__device__ __align__(16) __half g_w1h[HID_CH * IN_CH];
__device__ __align__(16) __half g_w2h[IN_CH * HID_CH];
__device__ __align__(16) float  g_bias1[HID_CH];
__device__ __align__(16) float  g_part[1024 * 384];
__device__ __align__(16) float  g_bns[IN_CH];
__device__ __align__(16) float  g_bnb[IN_CH];

// ---------------- helpers ----------------------------------------------------
__device__ __forceinline__ uint32_t smem_u32(const void* p) {
    uint32_t a;
    asm("{ .reg .u64 tmp; cvta.to.shared.u64 tmp, %1; cvt.u32.u64 %0, tmp; }"
        : "=r"(a) : "l"(p));
    return a;
}
#define CP_ASYNC16(dst, src) \
    asm volatile("cp.async.cg.shared.global [%0], [%1], 16;" :: "r"(dst), "l"(src))
#define CP_COMMIT()  asm volatile("cp.async.commit_group;" ::: "memory")
#define CP_WAIT2()   asm volatile("cp.async.wait_group 2;" ::: "memory")

__device__ __forceinline__ void ldsm_x4(uint32_t& r0, uint32_t& r1,
                                        uint32_t& r2, uint32_t& r3, uint32_t addr) {
    asm volatile("ldmatrix.sync.aligned.m8n8.x4.shared.b16 {%0,%1,%2,%3}, [%4];"
        : "=r"(r0), "=r"(r1), "=r"(r2), "=r"(r3) : "r"(addr));
}

__device__ __forceinline__ void mma_f16(float* c, const uint32_t* a, const uint32_t* b) {
    asm volatile(
        "mma.sync.aligned.m16n8k16.row.col.f32.f16.f16.f32 "
        "{%0,%1,%2,%3}, {%4,%5,%6,%7}, {%8,%9}, {%0,%1,%2,%3};"
        : "+f"(c[0]), "+f"(c[1]), "+f"(c[2]), "+f"(c[3])
        : "r"(a[0]), "r"(a[1]), "r"(a[2]), "r"(a[3]), "r"(b[0]), "r"(b[1]));
}

// ---------------- Kernel 1: DWT + BN partials; LL straight into out ----------
__global__ void k_dwt(const float* __restrict__ x, float* __restrict__ out) {
    int bi = blockIdx.x;
    int b = bi >> 7, i = bi & 127;
    int t = threadIdx.x;
    int c = t & 63, jq = t >> 6;

    float s0=0,s1=0,s2=0,s3=0, q0=0,q1=0,q2=0,q3=0;
    const float* xr0 = x + (size_t)(b*256 + 2*i) * 256 * 64;
    const float* xr1 = xr0 + 256*64;
    float* orow0 = out + (size_t)(b*256 + 2*i) * 256 * 64;
    const bool isHigh = (c >= 16);
    const int f = 4*c;

    for (int j = jq; j < 128; j += 4) {
        int col = 2*j*64 + c;
        float a  = xr0[col],  bb = xr0[col+64];
        float cc = xr1[col],  dd = xr1[col+64];
        float ll = 0.5f*(a+bb+cc+dd);
        float lh = 0.5f*(a-bb+cc-dd);
        float hl = 0.5f*(a+bb-cc-dd);
        float hh = 0.5f*(a-bb-cc+dd);
        size_t p = (size_t)bi*128 + j;
        if (!isHigh) {
            *(float4*)(orow0 + 2*j*64 + f) = make_float4(ll, lh, hl, hh);
        } else {
            __half2 h0 = __floats2half2_rn(ll, lh);
            __half2 h1 = __floats2half2_rn(hl, hh);
            uint2 u;
            u.x = *(uint32_t*)&h0;
            u.y = *(uint32_t*)&h1;
            *(uint2*)(g_high_h + p*192 + (f - 64)) = u;
            s0 += ll; s1 += lh; s2 += hl; s3 += hh;
            q0 += ll*ll; q1 += lh*lh; q2 += hl*hl; q3 += hh*hh;
        }
    }

    __shared__ float red[256][8];
    red[t][0]=s0; red[t][1]=s1; red[t][2]=s2; red[t][3]=s3;
    red[t][4]=q0; red[t][5]=q1; red[t][6]=q2; red[t][7]=q3;
    __syncthreads();
    if (t >= 16 && t < 64) {
        #pragma unroll
        for (int k = 0; k < 4; k++) {
            float sv = red[t][k]   + red[64+t][k]   + red[128+t][k]   + red[192+t][k];
            float qv = red[t][4+k] + red[64+t][4+k] + red[128+t][4+k] + red[192+t][4+k];
            int m = 4*(t-16) + k;
            g_part[(size_t)bi*384 + m]       = sv;
            g_part[(size_t)bi*384 + 192 + m] = qv;
        }
    }
}

// ---------------- Kernel 2: BN finalize --------------------------------------
__global__ void k_bnfin(const float* __restrict__ gamma,
                        const float* __restrict__ beta) {
    int t = threadIdx.x;  // 384
    float s = 0.f;
    for (int r = 0; r < 1024; r++) s += g_part[(size_t)r*384 + t];
    __shared__ float sm[384];
    sm[t] = s;
    __syncthreads();
    if (t < 192) {
        const float N = (float)P_TOT;
        float mean = sm[t] / N;
        float var  = sm[t+192] / N - mean*mean;
        float sc   = gamma[t] * rsqrtf(var + 1e-5f);
        g_bns[t] = sc;
        g_bnb[t] = beta[t] - mean * sc;
    }
}

// ---------------- Kernel 3: weight prep (BN fold + half convert) -------------
__global__ void k_wprep(const float* __restrict__ w_in,
                        const float* __restrict__ w_out) {
    int b = blockIdx.x, t = threadIdx.x;   // 192 threads
    if (b < 384) {
        float wv = w_in[b*192 + t];
        g_w1h[b*192 + t] = __float2half_rn(wv * g_bns[t]);
        float p = wv * g_bnb[t];
        #pragma unroll
        for (int o = 16; o; o >>= 1) p += __shfl_down_sync(0xffffffffu, p, o);
        __shared__ float sw[6];
        if ((t & 31) == 0) sw[t >> 5] = p;
        __syncthreads();
        if (t == 0)
            g_bias1[b] = sw[0]+sw[1]+sw[2]+sw[3]+sw[4]+sw[5];
    } else {
        int i = (b - 384)*192 + t;
        g_w2h[i] = __float2half_rn(w_out[i]);
    }
}

// ---------------- fp16 MMA GEMM: BM=64, BN=192, BK=16, 3-stage cp.async ------
// smem row: 8 data words + 4 pad -> stride 12. Stage = (64+192)*12 words = 12KB.
template<int LDK>
__device__ __forceinline__ void gemm_prefetch(uint32_t smem_base,
                                              const __half* __restrict__ A,
                                              const __half* __restrict__ W,
                                              size_t pbase, int t, int ic, int stage) {
    constexpr int AW  = 64 * 12;
    constexpr int STG = AW + 192 * 12;
    const int kc = ic * 16;
    if (t < 128) {
        int row = t >> 1, seg = t & 1;
        uint32_t dst = smem_base + (uint32_t)(stage*STG + row*12 + seg*4) * 4;
        CP_ASYNC16(dst, A + (pbase + row)*LDK + kc + seg*8);
    }
    {
        int f = t + 128;   // threads 128..255 -> first 128 W rows' segs... need 384 units
    }
    #pragma unroll
    for (int s = 0; s < 2; s++) {       // 384 (n,seg) units over 256 threads
        int f = t + 256*s;
        if (f < 384) {
            int n = f >> 1, seg = f & 1;
            uint32_t dst = smem_base + (uint32_t)(stage*STG + AW + n*12 + seg*4) * 4;
            CP_ASYNC16(dst, W + (size_t)n*LDK + kc + seg*8);
        }
    }
}

// MODE 0: +bias, store half to out_h (row stride 384, col offset obase).
// MODE 1: residual + fused pixel-shuffle scatter to out_f.
template<int LDK, int MODE>
__device__ __forceinline__ void gemm_core(const __half* __restrict__ A,
                                          const __half* __restrict__ W,
                                          int obase,
                                          __half* __restrict__ out_h,
                                          float* __restrict__ out_f,
                                          const float* __restrict__ res_scale) {
    constexpr int NT  = 6;
    constexpr int NC  = LDK / 16;
    constexpr int AW  = 64 * 12;
    constexpr int STG = AW + 192 * 12;

    extern __shared__ uint32_t smw[];
    const uint32_t smem_base = smem_u32(smw);

    const int t = threadIdx.x;
    const int lane = t & 31, wp = t >> 5;
    const int g = lane >> 2, qi = lane & 3;
    const int warpM = (wp & 1) * 32;
    const int warpN = (wp >> 1) * 48;
    const size_t pbase = (size_t)blockIdx.y * 64;

    uint32_t aAddr[2];
    #pragma unroll
    for (int mt = 0; mt < 2; mt++) {
        int row  = warpM + mt*16 + (lane & 7) + ((lane >> 3) & 1) * 8;
        int word = (lane & 16) ? 4 : 0;
        aAddr[mt] = smem_base + (uint32_t)(row*12 + word) * 4;
    }
    uint32_t bAddr[3];
    #pragma unroll
    for (int ntp = 0; ntp < 3; ntp++) {
        int row  = warpN + ntp*16 + ((lane >> 4) & 1) * 8 + (lane & 7);
        int word = ((lane >> 3) & 1) * 4;
        bAddr[ntp] = smem_base + (uint32_t)(AW + row*12 + word) * 4;
    }

    float c[2][NT][4];
    #pragma unroll
    for (int mt = 0; mt < 2; mt++)
        #pragma unroll
        for (int nt = 0; nt < NT; nt++)
            #pragma unroll
            for (int q = 0; q < 4; q++) c[mt][nt][q] = 0.f;

    gemm_prefetch<LDK>(smem_base, A, W, pbase, t, 0, 0);
    CP_COMMIT();
    gemm_prefetch<LDK>(smem_base, A, W, pbase, t, 1, 1);
    CP_COMMIT();

    int st = 0;
    for (int ic = 0; ic < NC; ic++) {
        if (ic + 2 < NC) {
            int ns = st + 2; if (ns >= 3) ns -= 3;
            gemm_prefetch<LDK>(smem_base, A, W, pbase, t, ic+2, ns);
        }
        CP_COMMIT();        // empty group when no prefetch -> uniform wait count
        CP_WAIT2();
        __syncthreads();

        const uint32_t soff = (uint32_t)(st * STG * 4);
        uint32_t a[2][4];
        ldsm_x4(a[0][0], a[0][1], a[0][2], a[0][3], aAddr[0] + soff);
        ldsm_x4(a[1][0], a[1][1], a[1][2], a[1][3], aAddr[1] + soff);
        #pragma unroll
        for (int ntp = 0; ntp < 3; ntp++) {
            uint32_t b0, b1, b2, b3;
            ldsm_x4(b0, b1, b2, b3, bAddr[ntp] + soff);
            uint32_t bb0[2] = {b0, b1}, bb1[2] = {b2, b3};
            mma_f16(c[0][2*ntp],   a[0], bb0);
            mma_f16(c[1][2*ntp],   a[1], bb0);
            mma_f16(c[0][2*ntp+1], a[0], bb1);
            mma_f16(c[1][2*ntp+1], a[1], bb1);
        }
        __syncthreads();
        if (++st == 3) st = 0;
    }

    if (MODE == 0) {
        #pragma unroll
        for (int mt = 0; mt < 2; mt++) {
            #pragma unroll
            for (int hi = 0; hi < 2; hi++) {
                int row = warpM + mt*16 + g + hi*8;
                __half* orow = out_h + (pbase + row) * 384 + obase;
                #pragma unroll
                for (int nt = 0; nt < NT; nt++) {
                    int col = warpN + nt*8 + qi*2;
                    float2 bv = *(const float2*)(g_bias1 + obase + col);
                    __half2 hv = __floats2half2_rn(c[mt][nt][hi*2]   + bv.x,
                                                   c[mt][nt][hi*2+1] + bv.y);
                    *(__half2*)(orow + col) = hv;
                }
            }
        }
    } else {
        const float rs = __ldg(res_scale);
        #pragma unroll
        for (int mt = 0; mt < 2; mt++) {
            #pragma unroll
            for (int hi = 0; hi < 2; hi++) {
                int row = warpM + mt*16 + g + hi*8;
                size_t p = pbase + row;
                int bi = (int)(p >> 7);
                int j  = (int)(p & 127);
                int b  = bi >> 7, i = bi & 127;
                const __half* hrow = g_high_h + p*192;
                size_t base = ((size_t)(b*256 + 2*i) * 256 + 2*j) * 64;
                #pragma unroll
                for (int nt = 0; nt < NT; nt++) {
                    int col = warpN + nt*8 + qi*2;
                    int gq = col >> 6, cc = col & 63;
                    float2 hv = __half22float2(*(const __half2*)(hrow + col));
                    float v0 = fmaf(rs, c[mt][nt][hi*2 + 0], hv.x);
                    float v1 = fmaf(rs, c[mt][nt][hi*2 + 1], hv.y);
                    size_t addr = base + cc
                                + ((gq >= 1) ? (size_t)256*64 : 0)
                                + ((gq != 1) ? 64 : 0);
                    *(float2*)(out_f + addr) = make_float2(v0, v1);
                }
            }
        }
    }
}

// grid (2, 2048): x = n-block (adjacent CTAs share the A tile via L2), y = p-block
__global__ void __launch_bounds__(256, 2) k_gemm1() {
    int obase = blockIdx.x * 192;
    gemm_core<192, 0>(g_high_h, g_w1h + (size_t)obase*192, obase,
                      g_hid_h, nullptr, nullptr);
}
// grid (1, 2048)
__global__ void __launch_bounds__(256, 2) k_gemm2(float* __restrict__ out,
                                                  const float* __restrict__ rs) {
    gemm_core<384, 1>(g_act_h, g_w2h, 0, nullptr, out, rs);
}

// ---------------- Kernel 4: depthwise 3x3 + exact GELU (half in/out) ---------
__global__ void k_dw(const float* __restrict__ w_dw) {
    int bi = blockIdx.x;
    int i  = bi & 127;
    int ch = threadIdx.x * 4;
    int jb = threadIdx.y * 32;

    float w[3][3][4];
    #pragma unroll
    for (int r = 0; r < 3; r++)
        #pragma unroll
        for (int cc = 0; cc < 3; cc++)
            #pragma unroll
            for (int q = 0; q < 4; q++)
                w[r][cc][q] = w_dw[(ch+q)*9 + r*3 + cc];

    const __half* r1 = g_hid_h + (size_t)bi*49152 + ch;
    const __half* r0 = r1 - 49152;
    const __half* r2 = r1 + 49152;
    const bool up = (i > 0), dn = (i < 127);

    float L[3][4], M[3][4], R[3][4];

#define DW_CVT(dst, u) do {                                                   \
    __half2 _h0 = *(__half2*)&(u).x, _h1 = *(__half2*)&(u).y;                 \
    float2 _f0 = __half22float2(_h0), _f1 = __half22float2(_h1);              \
    dst[0] = _f0.x; dst[1] = _f0.y; dst[2] = _f1.x; dst[3] = _f1.y;           \
} while (0)

#define DW_LOADCOL(dst, jj) do {                                              \
    if ((jj) >= 0 && (jj) < 128) {                                            \
        uint2 _zz = make_uint2(0, 0);                                         \
        uint2 _ua = up ? *(const uint2*)(r0 + (size_t)(jj)*384) : _zz;        \
        uint2 _ub = *(const uint2*)(r1 + (size_t)(jj)*384);                   \
        uint2 _uc = dn ? *(const uint2*)(r2 + (size_t)(jj)*384) : _zz;        \
        DW_CVT(dst[0], _ua); DW_CVT(dst[1], _ub); DW_CVT(dst[2], _uc);        \
    } else {                                                                  \
        _Pragma("unroll") for (int _r = 0; _r < 3; _r++)                      \
            _Pragma("unroll") for (int _q = 0; _q < 4; _q++) dst[_r][_q] = 0.f; \
    } } while (0)

    DW_LOADCOL(L, jb-1);
    DW_LOADCOL(M, jb);

    __half* obase = g_act_h + (size_t)bi*128*384 + ch;
    for (int j = jb; j < jb + 32; j++) {
        DW_LOADCOL(R, j+1);
        float s[4];
        #pragma unroll
        for (int q = 0; q < 4; q++) {
            float v = L[0][q]*w[0][0][q] + M[0][q]*w[0][1][q] + R[0][q]*w[0][2][q]
                    + L[1][q]*w[1][0][q] + M[1][q]*w[1][1][q] + R[1][q]*w[1][2][q]
                    + L[2][q]*w[2][0][q] + M[2][q]*w[2][1][q] + R[2][q]*w[2][2][q];
            s[q] = 0.5f * v * (1.f + erff(v * 0.70710678118654752f));
        }
        __half2 h0 = __floats2half2_rn(s[0], s[1]);
        __half2 h1 = __floats2half2_rn(s[2], s[3]);
        uint2 u;
        u.x = *(uint32_t*)&h0;
        u.y = *(uint32_t*)&h1;
        *(uint2*)(obase + (size_t)j*384) = u;
        #pragma unroll
        for (int r = 0; r < 3; r++)
            #pragma unroll
            for (int q = 0; q < 4; q++) { L[r][q] = M[r][q]; M[r][q] = R[r][q]; }
    }
#undef DW_LOADCOL
#undef DW_CVT
}

// ---------------- launch ------------------------------------------------------
extern "C" void kernel_launch(void* const* d_in, const int* in_sizes, int n_in,
                              void* d_out, int out_size) {
    const float* x     = (const float*)d_in[0];
    const float* gamma = (const float*)d_in[1];
    const float* beta  = (const float*)d_in[2];
    const float* w_in  = (const float*)d_in[3];
    const float* w_dw  = (const float*)d_in[4];
    const float* w_out = (const float*)d_in[5];
    const float* rs    = (const float*)d_in[6];
    float* out = (float*)d_out;

    const int SMG = 3 * (64*12 + 192*12) * 4;   // 36864 B (< 48K default)

    k_dwt  <<<1024, 256>>>(x, out);
    k_bnfin<<<1,    384>>>(gamma, beta);
    k_wprep<<<768,  192>>>(w_in, w_out);
    k_gemm1<<<dim3(2, 2048), 256, SMG>>>();
    k_dw   <<<1024, dim3(96, 4)>>>(w_dw);
    k_gemm2<<<dim3(1, 2048), 256, SMG>>>(out, rs);
}